// round 1
// baseline (speedup 1.0000x reference)
#include <cuda_runtime.h>
#include <math.h>

#define N_NODES  100000
#define N_HEDGES 100000
#define N_INC    3200000
#define N_LINKS  262144
#define C1 128
#define C2 256

// ---------------- device scratch (statically allocated; no cudaMalloc) ----------------
__device__ int   g_dv_cnt[N_NODES];
__device__ int   g_de_cnt[N_HEDGES];
__device__ int   g_node_off[N_NODES + 1];
__device__ int   g_edge_off[N_HEDGES + 1];
__device__ int   g_cursor[N_NODES];
__device__ int   g_node_edges[N_INC];
__device__ float g_dvi[N_NODES];    // Dv^{-1/2}
__device__ float g_dei[N_HEDGES];   // De^{-1}
__device__ float g_te[N_HEDGES];
__device__ float g_s[N_NODES];      // s = S*1
__device__ float g_zfc[N_NODES];
__device__ float g_X2[(size_t)N_NODES * C1];   // S*X
__device__ float g_h [(size_t)N_NODES * C2];   // relu((S X) W1 + s b1^T)
__device__ float g_t [(size_t)N_NODES * C1];   // h W2
__device__ float g_Ye[(size_t)N_HEDGES * C1];  // per-edge aggregate scratch

// ---------------- setup kernels ----------------
__global__ __launch_bounds__(256)
void zero_counts_kernel() {
    int i = blockIdx.x * 256 + threadIdx.x;
    if (i < N_NODES)  { g_dv_cnt[i] = 0; g_cursor[i] = 0; }
    if (i < N_HEDGES) { g_de_cnt[i] = 0; }
}

__global__ __launch_bounds__(256)
void count_kernel(const int* __restrict__ inc_v, const int* __restrict__ inc_e) {
    int i = blockIdx.x * 256 + threadIdx.x;
    if (i < N_INC) {
        atomicAdd(&g_dv_cnt[inc_v[i]], 1);
        atomicAdd(&g_de_cnt[inc_e[i]], 1);
    }
}

// single-block exclusive scan over n counts -> offsets, plus per-element inverse degree
// mode 0: inv = rsqrt(cnt) (nodes), mode 1: inv = 1/cnt (edges); 0 if cnt==0
__global__ __launch_bounds__(1024)
void scan_kernel(const int* __restrict__ cnt, int n, int* __restrict__ off,
                 float* __restrict__ inv_out, int mode) {
    __shared__ int ssum[1024];
    int t = threadIdx.x;
    int chunk = (n + 1023) >> 10;
    int beg = t * chunk;
    int end = beg + chunk; if (end > n) end = n;
    int local = 0;
    for (int i = beg; i < end; i++) local += cnt[i];
    ssum[t] = local;
    __syncthreads();
    for (int d = 1; d < 1024; d <<= 1) {
        int v = (t >= d) ? ssum[t - d] : 0;
        __syncthreads();
        ssum[t] += v;
        __syncthreads();
    }
    int run = (t > 0) ? ssum[t - 1] : 0;  // exclusive prefix
    for (int i = beg; i < end; i++) {
        off[i] = run;
        int c = cnt[i];
        run += c;
        if (mode == 0) inv_out[i] = (c > 0) ? rsqrtf((float)c) : 0.0f;
        else           inv_out[i] = (c > 0) ? 1.0f / (float)c : 0.0f;
    }
    if (t == 1023) off[n] = ssum[1023];
}

__global__ __launch_bounds__(256)
void build_csr_kernel(const int* __restrict__ inc_v, const int* __restrict__ inc_e) {
    int i = blockIdx.x * 256 + threadIdx.x;
    if (i < N_INC) {
        int v = inc_v[i];
        int pos = g_node_off[v] + atomicAdd(&g_cursor[v], 1);
        g_node_edges[pos] = inc_e[i];
    }
}

// te[e] = de_inv[e] * sum_{i in seg(e)} dvi[inc_v[i]]
__global__ __launch_bounds__(256)
void te_kernel(const int* __restrict__ inc_v) {
    int e = blockIdx.x * 256 + threadIdx.x;
    if (e >= N_HEDGES) return;
    int b = g_edge_off[e], en = g_edge_off[e + 1];
    float sum = 0.0f;
    for (int i = b; i < en; i++) sum += g_dvi[inc_v[i]];
    g_te[e] = g_dei[e] * sum;
}

// s[v] = dvi[v] * sum_{e in edges(v)} te[e]
__global__ __launch_bounds__(256)
void s_kernel() {
    int v = blockIdx.x * 256 + threadIdx.x;
    if (v >= N_NODES) return;
    int b = g_node_off[v], en = g_node_off[v + 1];
    float sum = 0.0f;
    for (int j = b; j < en; j++) sum += g_te[g_node_edges[j]];
    g_s[v] = g_dvi[v] * sum;
}

// ---------------- smoothing (C=128), one warp per edge/node ----------------
// Ye[e,:] = de_inv[e] * sum_{i in seg(e)} dvi[inc_v[i]] * Xin[inc_v[i],:]
__global__ __launch_bounds__(256)
void edge_agg_kernel(const float* __restrict__ Xin, const int* __restrict__ inc_v) {
    int w = (blockIdx.x * 256 + threadIdx.x) >> 5;
    int lane = threadIdx.x & 31;
    if (w >= N_HEDGES) return;
    int b = g_edge_off[w], e = g_edge_off[w + 1];
    float4 acc = make_float4(0.f, 0.f, 0.f, 0.f);
    int i = b;
    for (; i + 4 <= e; i += 4) {
        int u0 = inc_v[i], u1 = inc_v[i + 1], u2 = inc_v[i + 2], u3 = inc_v[i + 3];
        float w0 = g_dvi[u0], w1 = g_dvi[u1], w2 = g_dvi[u2], w3 = g_dvi[u3];
        float4 x0 = *(const float4*)(Xin + (size_t)u0 * C1 + lane * 4);
        float4 x1 = *(const float4*)(Xin + (size_t)u1 * C1 + lane * 4);
        float4 x2 = *(const float4*)(Xin + (size_t)u2 * C1 + lane * 4);
        float4 x3 = *(const float4*)(Xin + (size_t)u3 * C1 + lane * 4);
        acc.x = fmaf(w0, x0.x, acc.x); acc.y = fmaf(w0, x0.y, acc.y);
        acc.z = fmaf(w0, x0.z, acc.z); acc.w = fmaf(w0, x0.w, acc.w);
        acc.x = fmaf(w1, x1.x, acc.x); acc.y = fmaf(w1, x1.y, acc.y);
        acc.z = fmaf(w1, x1.z, acc.z); acc.w = fmaf(w1, x1.w, acc.w);
        acc.x = fmaf(w2, x2.x, acc.x); acc.y = fmaf(w2, x2.y, acc.y);
        acc.z = fmaf(w2, x2.z, acc.z); acc.w = fmaf(w2, x2.w, acc.w);
        acc.x = fmaf(w3, x3.x, acc.x); acc.y = fmaf(w3, x3.y, acc.y);
        acc.z = fmaf(w3, x3.z, acc.z); acc.w = fmaf(w3, x3.w, acc.w);
    }
    for (; i < e; i++) {
        int u = inc_v[i];
        float wu = g_dvi[u];
        float4 x = *(const float4*)(Xin + (size_t)u * C1 + lane * 4);
        acc.x = fmaf(wu, x.x, acc.x); acc.y = fmaf(wu, x.y, acc.y);
        acc.z = fmaf(wu, x.z, acc.z); acc.w = fmaf(wu, x.w, acc.w);
    }
    float d = g_dei[w];
    acc.x *= d; acc.y *= d; acc.z *= d; acc.w *= d;
    *(float4*)(g_Ye + (size_t)w * C1 + lane * 4) = acc;
}

// Xout[v,:] = dvi[v] * sum_{e in edges(v)} Ye[e,:]
__global__ __launch_bounds__(256)
void node_agg_kernel(float* __restrict__ Xout) {
    int v = (blockIdx.x * 256 + threadIdx.x) >> 5;
    int lane = threadIdx.x & 31;
    if (v >= N_NODES) return;
    int b = g_node_off[v], e = g_node_off[v + 1];
    float4 acc = make_float4(0.f, 0.f, 0.f, 0.f);
    int j = b;
    for (; j + 4 <= e; j += 4) {
        int e0 = g_node_edges[j], e1 = g_node_edges[j + 1];
        int e2 = g_node_edges[j + 2], e3 = g_node_edges[j + 3];
        float4 y0 = *(const float4*)(g_Ye + (size_t)e0 * C1 + lane * 4);
        float4 y1 = *(const float4*)(g_Ye + (size_t)e1 * C1 + lane * 4);
        float4 y2 = *(const float4*)(g_Ye + (size_t)e2 * C1 + lane * 4);
        float4 y3 = *(const float4*)(g_Ye + (size_t)e3 * C1 + lane * 4);
        acc.x += y0.x + y1.x + y2.x + y3.x;
        acc.y += y0.y + y1.y + y2.y + y3.y;
        acc.z += y0.z + y1.z + y2.z + y3.z;
        acc.w += y0.w + y1.w + y2.w + y3.w;
    }
    for (; j < e; j++) {
        int ee = g_node_edges[j];
        float4 y = *(const float4*)(g_Ye + (size_t)ee * C1 + lane * 4);
        acc.x += y.x; acc.y += y.y; acc.z += y.z; acc.w += y.w;
    }
    float d = g_dvi[v];
    acc.x *= d; acc.y *= d; acc.z *= d; acc.w *= d;
    *(float4*)(Xout + (size_t)v * C1 + lane * 4) = acc;
}

// final node pass: zfc[v] = sum_c relu(dvi[v]*agg_c + s[v]*b2[c]) * fcW[c]
__global__ __launch_bounds__(256)
void node_agg_final_kernel(const float* __restrict__ b2, const float* __restrict__ fcW) {
    int v = (blockIdx.x * 256 + threadIdx.x) >> 5;
    int lane = threadIdx.x & 31;
    if (v >= N_NODES) return;
    int b = g_node_off[v], e = g_node_off[v + 1];
    float4 acc = make_float4(0.f, 0.f, 0.f, 0.f);
    int j = b;
    for (; j + 4 <= e; j += 4) {
        int e0 = g_node_edges[j], e1 = g_node_edges[j + 1];
        int e2 = g_node_edges[j + 2], e3 = g_node_edges[j + 3];
        float4 y0 = *(const float4*)(g_Ye + (size_t)e0 * C1 + lane * 4);
        float4 y1 = *(const float4*)(g_Ye + (size_t)e1 * C1 + lane * 4);
        float4 y2 = *(const float4*)(g_Ye + (size_t)e2 * C1 + lane * 4);
        float4 y3 = *(const float4*)(g_Ye + (size_t)e3 * C1 + lane * 4);
        acc.x += y0.x + y1.x + y2.x + y3.x;
        acc.y += y0.y + y1.y + y2.y + y3.y;
        acc.z += y0.z + y1.z + y2.z + y3.z;
        acc.w += y0.w + y1.w + y2.w + y3.w;
    }
    for (; j < e; j++) {
        int ee = g_node_edges[j];
        float4 y = *(const float4*)(g_Ye + (size_t)ee * C1 + lane * 4);
        acc.x += y.x; acc.y += y.y; acc.z += y.z; acc.w += y.w;
    }
    float d  = g_dvi[v];
    float sv = g_s[v];
    float4 bb = *(const float4*)(b2 + lane * 4);
    float4 fw = *(const float4*)(fcW + lane * 4);
    float zx = fmaxf(fmaf(d, acc.x, sv * bb.x), 0.f);
    float zy = fmaxf(fmaf(d, acc.y, sv * bb.y), 0.f);
    float zz = fmaxf(fmaf(d, acc.z, sv * bb.z), 0.f);
    float zw = fmaxf(fmaf(d, acc.w, sv * bb.w), 0.f);
    float p = zx * fw.x + zy * fw.y + zz * fw.z + zw * fw.w;
    #pragma unroll
    for (int o = 16; o > 0; o >>= 1) p += __shfl_down_sync(0xffffffffu, p, o);
    if (lane == 0) g_zfc[v] = p;
}

// ---------------- SGEMM: C = A[M,K] @ B[K,N] (+ rowscale[m]*bias[n]) (relu) ----------------
#define BM 128
#define BN 128
#define BKK 16
#define TM 8
#define TN 8

__global__ __launch_bounds__(256, 2)
void sgemm_kernel(const float* __restrict__ A, const float* __restrict__ B,
                  float* __restrict__ Cout, int M, int N, int K,
                  const float* __restrict__ bias, const float* __restrict__ rowscale,
                  int do_relu) {
    __shared__ float As[BKK][BM + 4];
    __shared__ float Bs[BKK][BN];

    int block_row = blockIdx.x * BM;
    int block_col = blockIdx.y * BN;
    int tid = threadIdx.x;
    int tx = tid % (BN / TN);   // 0..15
    int ty = tid / (BN / TN);   // 0..15

    int a_row = tid >> 2;             // 0..63
    int a_col = (tid & 3) * 4;        // 0,4,8,12
    int b_row = tid >> 5;             // 0..7
    int b_col = (tid & 31) * 4;       // 0..124

    float acc[TM][TN] = {};

    for (int k0 = 0; k0 < K; k0 += BKK) {
        #pragma unroll
        for (int r = 0; r < 2; r++) {
            int row = a_row + r * 64;
            int grow = block_row + row;
            float4 v = make_float4(0.f, 0.f, 0.f, 0.f);
            if (grow < M)
                v = *(const float4*)(A + (size_t)grow * K + k0 + a_col);
            As[a_col + 0][row] = v.x;
            As[a_col + 1][row] = v.y;
            As[a_col + 2][row] = v.z;
            As[a_col + 3][row] = v.w;
        }
        #pragma unroll
        for (int r = 0; r < 2; r++) {
            int kr = b_row + r * 8;
            float4 v = *(const float4*)(B + (size_t)(k0 + kr) * N + block_col + b_col);
            *(float4*)(&Bs[kr][b_col]) = v;
        }
        __syncthreads();
        #pragma unroll
        for (int kk = 0; kk < BKK; kk++) {
            float am[TM], bn[TN];
            #pragma unroll
            for (int i = 0; i < TM; i++) am[i] = As[kk][ty * TM + i];
            #pragma unroll
            for (int jj = 0; jj < TN; jj++) bn[jj] = Bs[kk][tx * TN + jj];
            #pragma unroll
            for (int i = 0; i < TM; i++)
                #pragma unroll
                for (int jj = 0; jj < TN; jj++)
                    acc[i][jj] = fmaf(am[i], bn[jj], acc[i][jj]);
        }
        __syncthreads();
    }

    #pragma unroll
    for (int i = 0; i < TM; i++) {
        int grow = block_row + ty * TM + i;
        if (grow >= M) continue;
        float rs = rowscale ? rowscale[grow] : 0.f;
        #pragma unroll
        for (int jj = 0; jj < TN; jj += 4) {
            int gcol = block_col + tx * TN + jj;
            float4 v;
            v.x = acc[i][jj + 0]; v.y = acc[i][jj + 1];
            v.z = acc[i][jj + 2]; v.w = acc[i][jj + 3];
            if (bias) {
                v.x = fmaf(rs, bias[gcol + 0], v.x);
                v.y = fmaf(rs, bias[gcol + 1], v.y);
                v.z = fmaf(rs, bias[gcol + 2], v.z);
                v.w = fmaf(rs, bias[gcol + 3], v.w);
            }
            if (do_relu) {
                v.x = fmaxf(v.x, 0.f); v.y = fmaxf(v.y, 0.f);
                v.z = fmaxf(v.z, 0.f); v.w = fmaxf(v.w, 0.f);
            }
            *(float4*)(Cout + (size_t)grow * N + gcol) = v;
        }
    }
}

// ---------------- link scoring ----------------
__global__ __launch_bounds__(256)
void link_kernel(const int* __restrict__ link, const float* __restrict__ fcb,
                 float* __restrict__ out) {
    int i = blockIdx.x * 256 + threadIdx.x;
    if (i >= N_LINKS) return;
    int a = link[2 * i], b = link[2 * i + 1];
    float x = (g_zfc[a] + g_zfc[b]) * 0.5f + fcb[0];
    out[i] = 1.0f / (1.0f + __expf(-x));
}

// ---------------- launch ----------------
extern "C" void kernel_launch(void* const* d_in, const int* in_sizes, int n_in,
                              void* d_out, int out_size) {
    const float* X    = (const float*)d_in[0];
    const float* W1   = (const float*)d_in[1];
    const float* b1   = (const float*)d_in[2];
    const float* W2   = (const float*)d_in[3];
    const float* b2   = (const float*)d_in[4];
    const float* fcW  = (const float*)d_in[5];
    const float* fcb  = (const float*)d_in[6];
    const int*   incv = (const int*)d_in[7];
    const int*   ince = (const int*)d_in[8];
    const int*   link = (const int*)d_in[9];
    float* out = (float*)d_out;

    static int*   p_dv_cnt = nullptr;
    static int*   p_de_cnt = nullptr;
    static int*   p_node_off = nullptr;
    static int*   p_edge_off = nullptr;
    static float* p_dvi = nullptr;
    static float* p_dei = nullptr;
    static float* p_s   = nullptr;
    static float* p_X2  = nullptr;
    static float* p_h   = nullptr;
    static float* p_t   = nullptr;
    if (!p_dv_cnt) {
        cudaGetSymbolAddress((void**)&p_dv_cnt, g_dv_cnt);
        cudaGetSymbolAddress((void**)&p_de_cnt, g_de_cnt);
        cudaGetSymbolAddress((void**)&p_node_off, g_node_off);
        cudaGetSymbolAddress((void**)&p_edge_off, g_edge_off);
        cudaGetSymbolAddress((void**)&p_dvi, g_dvi);
        cudaGetSymbolAddress((void**)&p_dei, g_dei);
        cudaGetSymbolAddress((void**)&p_s,   g_s);
        cudaGetSymbolAddress((void**)&p_X2,  g_X2);
        cudaGetSymbolAddress((void**)&p_h,   g_h);
        cudaGetSymbolAddress((void**)&p_t,   g_t);
    }

    const int TPB = 256;
    int inc_blocks    = (N_INC + TPB - 1) / TPB;
    int node_blocks   = (N_NODES + TPB - 1) / TPB;
    int warp_blocks_e = (N_HEDGES * 32 + TPB - 1) / TPB;
    int warp_blocks_n = (N_NODES * 32 + TPB - 1) / TPB;

    // 1. degrees + CSR
    zero_counts_kernel<<<node_blocks, TPB>>>();
    count_kernel<<<inc_blocks, TPB>>>(incv, ince);
    scan_kernel<<<1, 1024>>>(p_dv_cnt, N_NODES, p_node_off, p_dvi, 0);
    scan_kernel<<<1, 1024>>>(p_de_cnt, N_HEDGES, p_edge_off, p_dei, 1);
    build_csr_kernel<<<inc_blocks, TPB>>>(incv, ince);

    // 2. s = S * 1
    te_kernel<<<node_blocks, TPB>>>(incv);
    s_kernel<<<node_blocks, TPB>>>();

    // 3. X2 = S * X   (smooth at C=128, before GEMM1)
    edge_agg_kernel<<<warp_blocks_e, TPB>>>(X, incv);
    node_agg_kernel<<<warp_blocks_n, TPB>>>(p_X2);

    // 4. h = relu(X2 @ W1 + s*b1)  [N,256]
    {
        dim3 grid((N_NODES + BM - 1) / BM, C2 / BN);
        sgemm_kernel<<<grid, 256>>>(p_X2, W1, p_h, N_NODES, C2, C1, b1, p_s, 1);
    }

    // 5. t = h @ W2   [N,128]
    {
        dim3 grid((N_NODES + BM - 1) / BM, C1 / BN);
        sgemm_kernel<<<grid, 256>>>(p_h, W2, p_t, N_NODES, C1, C2, nullptr, nullptr, 0);
    }

    // 6. smooth t, fused relu(+s*b2) dot fcW -> zfc
    edge_agg_kernel<<<warp_blocks_e, TPB>>>(p_t, incv);
    node_agg_final_kernel<<<warp_blocks_n, TPB>>>(b2, fcW);

    // 7. link scores
    link_kernel<<<(N_LINKS + TPB - 1) / TPB, TPB>>>(link, fcb, out);
    (void)in_sizes; (void)n_in; (void)out_size;
}

// round 2
// speedup vs baseline: 2.1164x; 2.1164x over previous
#include <cuda_runtime.h>
#include <math.h>

#define N_NODES  100000
#define N_HEDGES 100000
#define N_INC    3200000
#define N_LINKS  262144
#define C1 128
#define C2 256

#define SCAN_ELEMS 1024
#define SCAN_BLOCKS ((N_NODES + SCAN_ELEMS - 1) / SCAN_ELEMS)   // 98

// ---------------- device scratch (static; no cudaMalloc) ----------------
__device__ int   g_dv_cnt[N_NODES];
__device__ int   g_node_off[N_NODES + 1];
__device__ int   g_edge_off[N_HEDGES + 1];
__device__ int   g_cursor[N_NODES];
__device__ int   g_node_edges[N_INC];
__device__ int   g_blk_sums[SCAN_BLOCKS];
__device__ int   g_blk_offs[SCAN_BLOCKS];
__device__ float g_dvi[N_NODES];    // Dv^{-1/2}
__device__ float g_dei[N_HEDGES];   // De^{-1}
__device__ float g_te[N_HEDGES];
__device__ float g_s[N_NODES];      // s = S*1
__device__ float g_zfc[N_NODES];
__device__ float g_X2[(size_t)N_NODES * C1];   // S*X
__device__ float g_h [(size_t)N_NODES * C2];   // relu((S X) W1 + s b1^T)
__device__ float g_t [(size_t)N_NODES * C1];   // h W2
__device__ float g_Ye[(size_t)N_HEDGES * C1];  // per-edge aggregate scratch

// ---------------- setup kernels ----------------
__global__ __launch_bounds__(256)
void zero_counts_kernel() {
    int i = blockIdx.x * 256 + threadIdx.x;
    if (i < N_NODES) { g_dv_cnt[i] = 0; g_cursor[i] = 0; }
}

__global__ __launch_bounds__(256)
void count_kernel(const int* __restrict__ inc_v) {
    int i = blockIdx.x * 256 + threadIdx.x;
    if (i < N_INC) atomicAdd(&g_dv_cnt[inc_v[i]], 1);
}

// ---- hierarchical parallel scan over node counts ----
__global__ __launch_bounds__(256)
void node_scan_phase1() {
    int b = blockIdx.x, t = threadIdx.x;
    int base = b * SCAN_ELEMS + t * 4;
    int s = 0;
    #pragma unroll
    for (int k = 0; k < 4; k++) {
        int i = base + k;
        if (i < N_NODES) s += g_dv_cnt[i];
    }
    __shared__ int sh[256];
    sh[t] = s; __syncthreads();
    #pragma unroll
    for (int d = 128; d > 0; d >>= 1) {
        if (t < d) sh[t] += sh[t + d];
        __syncthreads();
    }
    if (t == 0) g_blk_sums[b] = sh[0];
}

__global__ __launch_bounds__(128)
void node_scan_phase2() {
    int t = threadIdx.x;
    __shared__ int sh[128];
    int v = (t < SCAN_BLOCKS) ? g_blk_sums[t] : 0;
    sh[t] = v; __syncthreads();
    #pragma unroll
    for (int d = 1; d < 128; d <<= 1) {
        int x = (t >= d) ? sh[t - d] : 0;
        __syncthreads();
        sh[t] += x;
        __syncthreads();
    }
    if (t < SCAN_BLOCKS) g_blk_offs[t] = sh[t] - v;   // exclusive
    if (t == 127) g_node_off[N_NODES] = sh[127];      // total
}

__global__ __launch_bounds__(256)
void node_scan_phase3() {
    int b = blockIdx.x, t = threadIdx.x;
    int base = b * SCAN_ELEMS + t * 4;
    int c[4]; int s = 0;
    #pragma unroll
    for (int k = 0; k < 4; k++) {
        int i = base + k;
        c[k] = (i < N_NODES) ? g_dv_cnt[i] : 0;
        s += c[k];
    }
    __shared__ int sh[256];
    sh[t] = s; __syncthreads();
    #pragma unroll
    for (int d = 1; d < 256; d <<= 1) {
        int x = (t >= d) ? sh[t - d] : 0;
        __syncthreads();
        sh[t] += x;
        __syncthreads();
    }
    int run = g_blk_offs[b] + sh[t] - s;   // exclusive prefix at first elem
    #pragma unroll
    for (int k = 0; k < 4; k++) {
        int i = base + k;
        if (i < N_NODES) {
            g_node_off[i] = run;
            run += c[k];
            g_dvi[i] = (c[k] > 0) ? rsqrtf((float)c[k]) : 0.0f;
        }
    }
}

// edge offsets by binary search (inc_e is sorted)
__global__ __launch_bounds__(256)
void edge_off_kernel(const int* __restrict__ inc_e) {
    int e = blockIdx.x * 256 + threadIdx.x;
    if (e > N_HEDGES) return;
    int lo = 0, hi = N_INC;
    while (lo < hi) {
        int mid = (lo + hi) >> 1;
        if (inc_e[mid] < e) lo = mid + 1; else hi = mid;
    }
    g_edge_off[e] = lo;
}

__global__ __launch_bounds__(256)
void build_csr_kernel(const int* __restrict__ inc_v, const int* __restrict__ inc_e) {
    int i = blockIdx.x * 256 + threadIdx.x;
    if (i < N_INC) {
        int v = inc_v[i];
        int pos = g_node_off[v] + atomicAdd(&g_cursor[v], 1);
        g_node_edges[pos] = inc_e[i];
    }
}

// te[e] = de_inv[e] * sum_{i in seg(e)} dvi[inc_v[i]] ; also writes dei
__global__ __launch_bounds__(256)
void te_kernel(const int* __restrict__ inc_v) {
    int e = blockIdx.x * 256 + threadIdx.x;
    if (e >= N_HEDGES) return;
    int b = g_edge_off[e], en = g_edge_off[e + 1];
    float sum = 0.0f;
    for (int i = b; i < en; i++) sum += g_dvi[inc_v[i]];
    float dei = (en > b) ? 1.0f / (float)(en - b) : 0.0f;
    g_dei[e] = dei;
    g_te[e] = dei * sum;
}

// s[v] = dvi[v] * sum_{e in edges(v)} te[e]
__global__ __launch_bounds__(256)
void s_kernel() {
    int v = blockIdx.x * 256 + threadIdx.x;
    if (v >= N_NODES) return;
    int b = g_node_off[v], en = g_node_off[v + 1];
    float sum = 0.0f;
    for (int j = b; j < en; j++) sum += g_te[g_node_edges[j]];
    g_s[v] = g_dvi[v] * sum;
}

// ---------------- smoothing (C=128), one warp per edge/node ----------------
__global__ __launch_bounds__(256)
void edge_agg_kernel(const float* __restrict__ Xin, const int* __restrict__ inc_v) {
    int w = (blockIdx.x * 256 + threadIdx.x) >> 5;
    int lane = threadIdx.x & 31;
    if (w >= N_HEDGES) return;
    int b = g_edge_off[w], e = g_edge_off[w + 1];
    float4 acc = make_float4(0.f, 0.f, 0.f, 0.f);
    int i = b;
    for (; i + 4 <= e; i += 4) {
        int u0 = inc_v[i], u1 = inc_v[i + 1], u2 = inc_v[i + 2], u3 = inc_v[i + 3];
        float w0 = g_dvi[u0], w1 = g_dvi[u1], w2 = g_dvi[u2], w3 = g_dvi[u3];
        float4 x0 = *(const float4*)(Xin + (size_t)u0 * C1 + lane * 4);
        float4 x1 = *(const float4*)(Xin + (size_t)u1 * C1 + lane * 4);
        float4 x2 = *(const float4*)(Xin + (size_t)u2 * C1 + lane * 4);
        float4 x3 = *(const float4*)(Xin + (size_t)u3 * C1 + lane * 4);
        acc.x = fmaf(w0, x0.x, acc.x); acc.y = fmaf(w0, x0.y, acc.y);
        acc.z = fmaf(w0, x0.z, acc.z); acc.w = fmaf(w0, x0.w, acc.w);
        acc.x = fmaf(w1, x1.x, acc.x); acc.y = fmaf(w1, x1.y, acc.y);
        acc.z = fmaf(w1, x1.z, acc.z); acc.w = fmaf(w1, x1.w, acc.w);
        acc.x = fmaf(w2, x2.x, acc.x); acc.y = fmaf(w2, x2.y, acc.y);
        acc.z = fmaf(w2, x2.z, acc.z); acc.w = fmaf(w2, x2.w, acc.w);
        acc.x = fmaf(w3, x3.x, acc.x); acc.y = fmaf(w3, x3.y, acc.y);
        acc.z = fmaf(w3, x3.z, acc.z); acc.w = fmaf(w3, x3.w, acc.w);
    }
    for (; i < e; i++) {
        int u = inc_v[i];
        float wu = g_dvi[u];
        float4 x = *(const float4*)(Xin + (size_t)u * C1 + lane * 4);
        acc.x = fmaf(wu, x.x, acc.x); acc.y = fmaf(wu, x.y, acc.y);
        acc.z = fmaf(wu, x.z, acc.z); acc.w = fmaf(wu, x.w, acc.w);
    }
    float d = g_dei[w];
    acc.x *= d; acc.y *= d; acc.z *= d; acc.w *= d;
    *(float4*)(g_Ye + (size_t)w * C1 + lane * 4) = acc;
}

__global__ __launch_bounds__(256)
void node_agg_kernel(float* __restrict__ Xout) {
    int v = (blockIdx.x * 256 + threadIdx.x) >> 5;
    int lane = threadIdx.x & 31;
    if (v >= N_NODES) return;
    int b = g_node_off[v], e = g_node_off[v + 1];
    float4 acc = make_float4(0.f, 0.f, 0.f, 0.f);
    int j = b;
    for (; j + 4 <= e; j += 4) {
        int e0 = g_node_edges[j], e1 = g_node_edges[j + 1];
        int e2 = g_node_edges[j + 2], e3 = g_node_edges[j + 3];
        float4 y0 = *(const float4*)(g_Ye + (size_t)e0 * C1 + lane * 4);
        float4 y1 = *(const float4*)(g_Ye + (size_t)e1 * C1 + lane * 4);
        float4 y2 = *(const float4*)(g_Ye + (size_t)e2 * C1 + lane * 4);
        float4 y3 = *(const float4*)(g_Ye + (size_t)e3 * C1 + lane * 4);
        acc.x += y0.x + y1.x + y2.x + y3.x;
        acc.y += y0.y + y1.y + y2.y + y3.y;
        acc.z += y0.z + y1.z + y2.z + y3.z;
        acc.w += y0.w + y1.w + y2.w + y3.w;
    }
    for (; j < e; j++) {
        int ee = g_node_edges[j];
        float4 y = *(const float4*)(g_Ye + (size_t)ee * C1 + lane * 4);
        acc.x += y.x; acc.y += y.y; acc.z += y.z; acc.w += y.w;
    }
    float d = g_dvi[v];
    acc.x *= d; acc.y *= d; acc.z *= d; acc.w *= d;
    *(float4*)(Xout + (size_t)v * C1 + lane * 4) = acc;
}

// final node pass: zfc[v] = sum_c relu(dvi[v]*agg_c + s[v]*b2[c]) * fcW[c]
__global__ __launch_bounds__(256)
void node_agg_final_kernel(const float* __restrict__ b2, const float* __restrict__ fcW) {
    int v = (blockIdx.x * 256 + threadIdx.x) >> 5;
    int lane = threadIdx.x & 31;
    if (v >= N_NODES) return;
    int b = g_node_off[v], e = g_node_off[v + 1];
    float4 acc = make_float4(0.f, 0.f, 0.f, 0.f);
    int j = b;
    for (; j + 4 <= e; j += 4) {
        int e0 = g_node_edges[j], e1 = g_node_edges[j + 1];
        int e2 = g_node_edges[j + 2], e3 = g_node_edges[j + 3];
        float4 y0 = *(const float4*)(g_Ye + (size_t)e0 * C1 + lane * 4);
        float4 y1 = *(const float4*)(g_Ye + (size_t)e1 * C1 + lane * 4);
        float4 y2 = *(const float4*)(g_Ye + (size_t)e2 * C1 + lane * 4);
        float4 y3 = *(const float4*)(g_Ye + (size_t)e3 * C1 + lane * 4);
        acc.x += y0.x + y1.x + y2.x + y3.x;
        acc.y += y0.y + y1.y + y2.y + y3.y;
        acc.z += y0.z + y1.z + y2.z + y3.z;
        acc.w += y0.w + y1.w + y2.w + y3.w;
    }
    for (; j < e; j++) {
        int ee = g_node_edges[j];
        float4 y = *(const float4*)(g_Ye + (size_t)ee * C1 + lane * 4);
        acc.x += y.x; acc.y += y.y; acc.z += y.z; acc.w += y.w;
    }
    float d  = g_dvi[v];
    float sv = g_s[v];
    float4 bb = *(const float4*)(b2 + lane * 4);
    float4 fw = *(const float4*)(fcW + lane * 4);
    float zx = fmaxf(fmaf(d, acc.x, sv * bb.x), 0.f);
    float zy = fmaxf(fmaf(d, acc.y, sv * bb.y), 0.f);
    float zz = fmaxf(fmaf(d, acc.z, sv * bb.z), 0.f);
    float zw = fmaxf(fmaf(d, acc.w, sv * bb.w), 0.f);
    float p = zx * fw.x + zy * fw.y + zz * fw.z + zw * fw.w;
    #pragma unroll
    for (int o = 16; o > 0; o >>= 1) p += __shfl_down_sync(0xffffffffu, p, o);
    if (lane == 0) g_zfc[v] = p;
}

// ---------------- SGEMM: C = A[M,K] @ B[K,N] (+ rowscale[m]*bias[n]) (relu) ----------------
#define BM 128
#define BN 128
#define BKK 16
#define TM 8
#define TN 8

__global__ __launch_bounds__(256, 2)
void sgemm_kernel(const float* __restrict__ A, const float* __restrict__ B,
                  float* __restrict__ Cout, int M, int N, int K,
                  const float* __restrict__ bias, const float* __restrict__ rowscale,
                  int do_relu) {
    __shared__ float As[BKK][BM + 4];
    __shared__ float Bs[BKK][BN];

    int block_row = blockIdx.x * BM;
    int block_col = blockIdx.y * BN;
    int tid = threadIdx.x;
    int tx = tid % (BN / TN);
    int ty = tid / (BN / TN);

    int a_row = tid >> 2;
    int a_col = (tid & 3) * 4;
    int b_row = tid >> 5;
    int b_col = (tid & 31) * 4;

    float acc[TM][TN] = {};

    for (int k0 = 0; k0 < K; k0 += BKK) {
        #pragma unroll
        for (int r = 0; r < 2; r++) {
            int row = a_row + r * 64;
            int grow = block_row + row;
            float4 v = make_float4(0.f, 0.f, 0.f, 0.f);
            if (grow < M)
                v = *(const float4*)(A + (size_t)grow * K + k0 + a_col);
            As[a_col + 0][row] = v.x;
            As[a_col + 1][row] = v.y;
            As[a_col + 2][row] = v.z;
            As[a_col + 3][row] = v.w;
        }
        #pragma unroll
        for (int r = 0; r < 2; r++) {
            int kr = b_row + r * 8;
            float4 v = *(const float4*)(B + (size_t)(k0 + kr) * N + block_col + b_col);
            *(float4*)(&Bs[kr][b_col]) = v;
        }
        __syncthreads();
        #pragma unroll
        for (int kk = 0; kk < BKK; kk++) {
            float am[TM], bn[TN];
            #pragma unroll
            for (int i = 0; i < TM; i++) am[i] = As[kk][ty * TM + i];
            #pragma unroll
            for (int jj = 0; jj < TN; jj++) bn[jj] = Bs[kk][tx * TN + jj];
            #pragma unroll
            for (int i = 0; i < TM; i++)
                #pragma unroll
                for (int jj = 0; jj < TN; jj++)
                    acc[i][jj] = fmaf(am[i], bn[jj], acc[i][jj]);
        }
        __syncthreads();
    }

    #pragma unroll
    for (int i = 0; i < TM; i++) {
        int grow = block_row + ty * TM + i;
        if (grow >= M) continue;
        float rs = rowscale ? rowscale[grow] : 0.f;
        #pragma unroll
        for (int jj = 0; jj < TN; jj += 4) {
            int gcol = block_col + tx * TN + jj;
            float4 v;
            v.x = acc[i][jj + 0]; v.y = acc[i][jj + 1];
            v.z = acc[i][jj + 2]; v.w = acc[i][jj + 3];
            if (bias) {
                v.x = fmaf(rs, bias[gcol + 0], v.x);
                v.y = fmaf(rs, bias[gcol + 1], v.y);
                v.z = fmaf(rs, bias[gcol + 2], v.z);
                v.w = fmaf(rs, bias[gcol + 3], v.w);
            }
            if (do_relu) {
                v.x = fmaxf(v.x, 0.f); v.y = fmaxf(v.y, 0.f);
                v.z = fmaxf(v.z, 0.f); v.w = fmaxf(v.w, 0.f);
            }
            *(float4*)(Cout + (size_t)grow * N + gcol) = v;
        }
    }
}

// ---------------- link scoring ----------------
__global__ __launch_bounds__(256)
void link_kernel(const int* __restrict__ link, const float* __restrict__ fcb,
                 float* __restrict__ out) {
    int i = blockIdx.x * 256 + threadIdx.x;
    if (i >= N_LINKS) return;
    int a = link[2 * i], b = link[2 * i + 1];
    float x = (g_zfc[a] + g_zfc[b]) * 0.5f + fcb[0];
    out[i] = 1.0f / (1.0f + __expf(-x));
}

// ---------------- launch ----------------
extern "C" void kernel_launch(void* const* d_in, const int* in_sizes, int n_in,
                              void* d_out, int out_size) {
    const float* X    = (const float*)d_in[0];
    const float* W1   = (const float*)d_in[1];
    const float* b1   = (const float*)d_in[2];
    const float* W2   = (const float*)d_in[3];
    const float* b2   = (const float*)d_in[4];
    const float* fcW  = (const float*)d_in[5];
    const float* fcb  = (const float*)d_in[6];
    const int*   incv = (const int*)d_in[7];
    const int*   ince = (const int*)d_in[8];
    const int*   link = (const int*)d_in[9];
    float* out = (float*)d_out;

    static float* p_s  = nullptr;
    static float* p_X2 = nullptr;
    static float* p_h  = nullptr;
    static float* p_t  = nullptr;
    if (!p_s) {
        cudaGetSymbolAddress((void**)&p_s,  g_s);
        cudaGetSymbolAddress((void**)&p_X2, g_X2);
        cudaGetSymbolAddress((void**)&p_h,  g_h);
        cudaGetSymbolAddress((void**)&p_t,  g_t);
    }

    const int TPB = 256;
    int inc_blocks    = (N_INC + TPB - 1) / TPB;
    int node_blocks   = (N_NODES + TPB - 1) / TPB;
    int edge_blocks   = (N_HEDGES + 1 + TPB - 1) / TPB;
    int warp_blocks_e = (N_HEDGES * 32 + TPB - 1) / TPB;
    int warp_blocks_n = (N_NODES * 32 + TPB - 1) / TPB;

    // 1. node degrees + offsets (parallel hierarchical scan)
    zero_counts_kernel<<<node_blocks, TPB>>>();
    count_kernel<<<inc_blocks, TPB>>>(incv);
    node_scan_phase1<<<SCAN_BLOCKS, TPB>>>();
    node_scan_phase2<<<1, 128>>>();
    node_scan_phase3<<<SCAN_BLOCKS, TPB>>>();

    // 2. edge offsets via binary search on sorted inc_e
    edge_off_kernel<<<edge_blocks, TPB>>>(ince);

    // 3. node CSR
    build_csr_kernel<<<inc_blocks, TPB>>>(incv, ince);

    // 4. s = S * 1 (te also writes dei)
    te_kernel<<<node_blocks, TPB>>>(incv);
    s_kernel<<<node_blocks, TPB>>>();

    // 5. X2 = S * X
    edge_agg_kernel<<<warp_blocks_e, TPB>>>(X, incv);
    node_agg_kernel<<<warp_blocks_n, TPB>>>(p_X2);

    // 6. h = relu(X2 @ W1 + s*b1)  [N,256]
    {
        dim3 grid((N_NODES + BM - 1) / BM, C2 / BN);
        sgemm_kernel<<<grid, 256>>>(p_X2, W1, p_h, N_NODES, C2, C1, b1, p_s, 1);
    }

    // 7. t = h @ W2   [N,128]
    {
        dim3 grid((N_NODES + BM - 1) / BM, C1 / BN);
        sgemm_kernel<<<grid, 256>>>(p_h, W2, p_t, N_NODES, C1, C2, nullptr, nullptr, 0);
    }

    // 8. smooth t, fused relu(+s*b2) dot fcW -> zfc
    edge_agg_kernel<<<warp_blocks_e, TPB>>>(p_t, incv);
    node_agg_final_kernel<<<warp_blocks_n, TPB>>>(b2, fcW);

    // 9. link scores
    link_kernel<<<(N_LINKS + TPB - 1) / TPB, TPB>>>(link, fcb, out);
    (void)in_sizes; (void)n_in; (void)out_size;
}

// round 4
// speedup vs baseline: 3.0165x; 1.4253x over previous
#include <cuda_runtime.h>
#include <cuda_fp16.h>
#include <math.h>
#include <stdint.h>

#define N_NODES  100000
#define N_HEDGES 100000
#define N_INC    3200000
#define N_LINKS  262144
#define C1 128
#define C2 256

#define SCAN_ELEMS 1024
#define SCAN_BLOCKS ((N_NODES + SCAN_ELEMS - 1) / SCAN_ELEMS)   // 98

// ---------------- device scratch (static; no cudaMalloc) ----------------
__device__ int   g_dv_cnt[N_NODES];
__device__ int   g_node_off[N_NODES + 1];
__device__ int   g_edge_off[N_HEDGES + 1];
__device__ int   g_cursor[N_NODES];
__device__ int   g_node_edges[N_INC];
__device__ int   g_blk_sums[SCAN_BLOCKS];
__device__ int   g_blk_offs[SCAN_BLOCKS];
__device__ float g_dvi[N_NODES];    // Dv^{-1/2}
__device__ float g_dei[N_HEDGES];   // De^{-1}
__device__ float g_te[N_HEDGES];
__device__ float g_s[N_NODES];      // s = S*1
__device__ float g_zfc[N_NODES];
__device__ __half g_X2h[(size_t)N_NODES * C1];   // S*X (fp16, GEMM1 input)
__device__ __half g_hh [(size_t)N_NODES * C2];   // h (fp16, GEMM2 input)
__device__ __half g_W1T[(size_t)C2 * C1];        // W1^T fp16 [256,128]
__device__ __half g_W2T[(size_t)C1 * C2];        // W2^T fp16 [128,256]
__device__ float g_t [(size_t)N_NODES * C1];     // h W2 (fp32, gathered)
__device__ float g_Ye[(size_t)N_HEDGES * C1];    // per-edge aggregate scratch

// ---------------- setup kernels ----------------
__global__ __launch_bounds__(256)
void zero_counts_kernel() {
    int i = blockIdx.x * 256 + threadIdx.x;
    if (i < N_NODES) { g_dv_cnt[i] = 0; g_cursor[i] = 0; }
}

__global__ __launch_bounds__(256)
void count_kernel(const int* __restrict__ inc_v) {
    int i = blockIdx.x * 256 + threadIdx.x;
    if (i < N_INC) atomicAdd(&g_dv_cnt[inc_v[i]], 1);
}

__global__ __launch_bounds__(256)
void node_scan_phase1() {
    int b = blockIdx.x, t = threadIdx.x;
    int base = b * SCAN_ELEMS + t * 4;
    int s = 0;
    #pragma unroll
    for (int k = 0; k < 4; k++) { int i = base + k; if (i < N_NODES) s += g_dv_cnt[i]; }
    __shared__ int sh[256];
    sh[t] = s; __syncthreads();
    #pragma unroll
    for (int d = 128; d > 0; d >>= 1) { if (t < d) sh[t] += sh[t + d]; __syncthreads(); }
    if (t == 0) g_blk_sums[b] = sh[0];
}

__global__ __launch_bounds__(128)
void node_scan_phase2() {
    int t = threadIdx.x;
    __shared__ int sh[128];
    int v = (t < SCAN_BLOCKS) ? g_blk_sums[t] : 0;
    sh[t] = v; __syncthreads();
    #pragma unroll
    for (int d = 1; d < 128; d <<= 1) {
        int x = (t >= d) ? sh[t - d] : 0; __syncthreads(); sh[t] += x; __syncthreads();
    }
    if (t < SCAN_BLOCKS) g_blk_offs[t] = sh[t] - v;
    if (t == 127) g_node_off[N_NODES] = sh[127];
}

__global__ __launch_bounds__(256)
void node_scan_phase3() {
    int b = blockIdx.x, t = threadIdx.x;
    int base = b * SCAN_ELEMS + t * 4;
    int c[4]; int s = 0;
    #pragma unroll
    for (int k = 0; k < 4; k++) { int i = base + k; c[k] = (i < N_NODES) ? g_dv_cnt[i] : 0; s += c[k]; }
    __shared__ int sh[256];
    sh[t] = s; __syncthreads();
    #pragma unroll
    for (int d = 1; d < 256; d <<= 1) {
        int x = (t >= d) ? sh[t - d] : 0; __syncthreads(); sh[t] += x; __syncthreads();
    }
    int run = g_blk_offs[b] + sh[t] - s;
    #pragma unroll
    for (int k = 0; k < 4; k++) {
        int i = base + k;
        if (i < N_NODES) {
            g_node_off[i] = run; run += c[k];
            g_dvi[i] = (c[k] > 0) ? rsqrtf((float)c[k]) : 0.0f;
        }
    }
}

__global__ __launch_bounds__(256)
void edge_off_kernel(const int* __restrict__ inc_e) {
    int e = blockIdx.x * 256 + threadIdx.x;
    if (e > N_HEDGES) return;
    int lo = 0, hi = N_INC;
    while (lo < hi) { int mid = (lo + hi) >> 1; if (inc_e[mid] < e) lo = mid + 1; else hi = mid; }
    g_edge_off[e] = lo;
}

__global__ __launch_bounds__(256)
void build_csr_kernel(const int* __restrict__ inc_v, const int* __restrict__ inc_e) {
    int i = blockIdx.x * 256 + threadIdx.x;
    if (i < N_INC) {
        int v = inc_v[i];
        int pos = g_node_off[v] + atomicAdd(&g_cursor[v], 1);
        g_node_edges[pos] = inc_e[i];
    }
}

__global__ __launch_bounds__(256)
void te_kernel(const int* __restrict__ inc_v) {
    int e = blockIdx.x * 256 + threadIdx.x;
    if (e >= N_HEDGES) return;
    int b = g_edge_off[e], en = g_edge_off[e + 1];
    float sum = 0.0f;
    for (int i = b; i < en; i++) sum += g_dvi[inc_v[i]];
    float dei = (en > b) ? 1.0f / (float)(en - b) : 0.0f;
    g_dei[e] = dei;
    g_te[e] = dei * sum;
}

__global__ __launch_bounds__(256)
void s_kernel() {
    int v = blockIdx.x * 256 + threadIdx.x;
    if (v >= N_NODES) return;
    int b = g_node_off[v], en = g_node_off[v + 1];
    float sum = 0.0f;
    for (int j = b; j < en; j++) sum += g_te[g_node_edges[j]];
    g_s[v] = g_dvi[v] * sum;
}

// weight transpose + fp16: out[n*K + k] = W[k*N + n]
__global__ __launch_bounds__(256)
void wt_kernel(const float* __restrict__ W, __half* __restrict__ out, int K, int N) {
    int i = blockIdx.x * 256 + threadIdx.x;
    if (i < K * N) {
        int n = i / K, k = i % K;
        out[i] = __float2half(W[k * N + n]);
    }
}

// ---------------- smoothing (C=128), one warp per edge/node ----------------
__global__ __launch_bounds__(256)
void edge_agg_kernel(const float* __restrict__ Xin, const int* __restrict__ inc_v) {
    int w = (blockIdx.x * 256 + threadIdx.x) >> 5;
    int lane = threadIdx.x & 31;
    if (w >= N_HEDGES) return;
    int b = g_edge_off[w], e = g_edge_off[w + 1];
    float4 acc = make_float4(0.f, 0.f, 0.f, 0.f);
    int i = b;
    for (; i + 4 <= e; i += 4) {
        int u0 = inc_v[i], u1 = inc_v[i + 1], u2 = inc_v[i + 2], u3 = inc_v[i + 3];
        float w0 = g_dvi[u0], w1 = g_dvi[u1], w2 = g_dvi[u2], w3 = g_dvi[u3];
        float4 x0 = *(const float4*)(Xin + (size_t)u0 * C1 + lane * 4);
        float4 x1 = *(const float4*)(Xin + (size_t)u1 * C1 + lane * 4);
        float4 x2 = *(const float4*)(Xin + (size_t)u2 * C1 + lane * 4);
        float4 x3 = *(const float4*)(Xin + (size_t)u3 * C1 + lane * 4);
        acc.x = fmaf(w0, x0.x, acc.x); acc.y = fmaf(w0, x0.y, acc.y);
        acc.z = fmaf(w0, x0.z, acc.z); acc.w = fmaf(w0, x0.w, acc.w);
        acc.x = fmaf(w1, x1.x, acc.x); acc.y = fmaf(w1, x1.y, acc.y);
        acc.z = fmaf(w1, x1.z, acc.z); acc.w = fmaf(w1, x1.w, acc.w);
        acc.x = fmaf(w2, x2.x, acc.x); acc.y = fmaf(w2, x2.y, acc.y);
        acc.z = fmaf(w2, x2.z, acc.z); acc.w = fmaf(w2, x2.w, acc.w);
        acc.x = fmaf(w3, x3.x, acc.x); acc.y = fmaf(w3, x3.y, acc.y);
        acc.z = fmaf(w3, x3.z, acc.z); acc.w = fmaf(w3, x3.w, acc.w);
    }
    for (; i < e; i++) {
        int u = inc_v[i];
        float wu = g_dvi[u];
        float4 x = *(const float4*)(Xin + (size_t)u * C1 + lane * 4);
        acc.x = fmaf(wu, x.x, acc.x); acc.y = fmaf(wu, x.y, acc.y);
        acc.z = fmaf(wu, x.z, acc.z); acc.w = fmaf(wu, x.w, acc.w);
    }
    float d = g_dei[w];
    acc.x *= d; acc.y *= d; acc.z *= d; acc.w *= d;
    *(float4*)(g_Ye + (size_t)w * C1 + lane * 4) = acc;
}

// node aggregation -> fp16 output (GEMM1 input)
__global__ __launch_bounds__(256)
void node_agg_h_kernel(__half* __restrict__ Xout) {
    int v = (blockIdx.x * 256 + threadIdx.x) >> 5;
    int lane = threadIdx.x & 31;
    if (v >= N_NODES) return;
    int b = g_node_off[v], e = g_node_off[v + 1];
    float4 acc = make_float4(0.f, 0.f, 0.f, 0.f);
    int j = b;
    for (; j + 4 <= e; j += 4) {
        int e0 = g_node_edges[j], e1 = g_node_edges[j + 1];
        int e2 = g_node_edges[j + 2], e3 = g_node_edges[j + 3];
        float4 y0 = *(const float4*)(g_Ye + (size_t)e0 * C1 + lane * 4);
        float4 y1 = *(const float4*)(g_Ye + (size_t)e1 * C1 + lane * 4);
        float4 y2 = *(const float4*)(g_Ye + (size_t)e2 * C1 + lane * 4);
        float4 y3 = *(const float4*)(g_Ye + (size_t)e3 * C1 + lane * 4);
        acc.x += y0.x + y1.x + y2.x + y3.x;
        acc.y += y0.y + y1.y + y2.y + y3.y;
        acc.z += y0.z + y1.z + y2.z + y3.z;
        acc.w += y0.w + y1.w + y2.w + y3.w;
    }
    for (; j < e; j++) {
        int ee = g_node_edges[j];
        float4 y = *(const float4*)(g_Ye + (size_t)ee * C1 + lane * 4);
        acc.x += y.x; acc.y += y.y; acc.z += y.z; acc.w += y.w;
    }
    float d = g_dvi[v];
    __half2* dst = (__half2*)(Xout + (size_t)v * C1 + lane * 4);
    dst[0] = __floats2half2_rn(acc.x * d, acc.y * d);
    dst[1] = __floats2half2_rn(acc.z * d, acc.w * d);
}

// final node pass: zfc[v] = sum_c relu(dvi[v]*agg_c + s[v]*b2[c]) * fcW[c]
__global__ __launch_bounds__(256)
void node_agg_final_kernel(const float* __restrict__ b2, const float* __restrict__ fcW) {
    int v = (blockIdx.x * 256 + threadIdx.x) >> 5;
    int lane = threadIdx.x & 31;
    if (v >= N_NODES) return;
    int b = g_node_off[v], e = g_node_off[v + 1];
    float4 acc = make_float4(0.f, 0.f, 0.f, 0.f);
    int j = b;
    for (; j + 4 <= e; j += 4) {
        int e0 = g_node_edges[j], e1 = g_node_edges[j + 1];
        int e2 = g_node_edges[j + 2], e3 = g_node_edges[j + 3];
        float4 y0 = *(const float4*)(g_Ye + (size_t)e0 * C1 + lane * 4);
        float4 y1 = *(const float4*)(g_Ye + (size_t)e1 * C1 + lane * 4);
        float4 y2 = *(const float4*)(g_Ye + (size_t)e2 * C1 + lane * 4);
        float4 y3 = *(const float4*)(g_Ye + (size_t)e3 * C1 + lane * 4);
        acc.x += y0.x + y1.x + y2.x + y3.x;
        acc.y += y0.y + y1.y + y2.y + y3.y;
        acc.z += y0.z + y1.z + y2.z + y3.z;
        acc.w += y0.w + y1.w + y2.w + y3.w;
    }
    for (; j < e; j++) {
        int ee = g_node_edges[j];
        float4 y = *(const float4*)(g_Ye + (size_t)ee * C1 + lane * 4);
        acc.x += y.x; acc.y += y.y; acc.z += y.z; acc.w += y.w;
    }
    float d  = g_dvi[v];
    float sv = g_s[v];
    float4 bb = *(const float4*)(b2 + lane * 4);
    float4 fw = *(const float4*)(fcW + lane * 4);
    float zx = fmaxf(fmaf(d, acc.x, sv * bb.x), 0.f);
    float zy = fmaxf(fmaf(d, acc.y, sv * bb.y), 0.f);
    float zz = fmaxf(fmaf(d, acc.z, sv * bb.z), 0.f);
    float zw = fmaxf(fmaf(d, acc.w, sv * bb.w), 0.f);
    float p = zx * fw.x + zy * fw.y + zz * fw.z + zw * fw.w;
    #pragma unroll
    for (int o = 16; o > 0; o >>= 1) p += __shfl_down_sync(0xffffffffu, p, o);
    if (lane == 0) g_zfc[v] = p;
}

// ---------------- mma.sync fp16 GEMM: C[M,N] = A[M,K] @ Bt[N,K]^T ----------------
// mode 1: outH = relu(C + rowscale[m]*bias[n]) as fp16
// mode 0: outF = C as fp32
#define GBK 32
#define GSTRIDE (GBK + 8)     // padded smem row stride in halves

__global__ __launch_bounds__(256)
void gemm_mma_kernel(const __half* __restrict__ A, const __half* __restrict__ Bt,
                     int M, int K, int N, int mode,
                     const float* __restrict__ rowscale, const float* __restrict__ bias,
                     __half* __restrict__ outH, float* __restrict__ outF) {
    __shared__ __half As[128 * GSTRIDE];
    __shared__ __half Bs[128 * GSTRIDE];

    int tid = threadIdx.x;
    int wid = tid >> 5, lane = tid & 31;
    int warp_m = wid >> 2;          // 0..1  (64-row slab)
    int warp_n = wid & 3;           // 0..3  (32-col slab)
    int gid = lane >> 2;            // 0..7
    int tig = lane & 3;             // 0..3

    int blockRow = blockIdx.x * 128;
    int blockCol = blockIdx.y * 128;

    float acc[4][4][4];
    #pragma unroll
    for (int i = 0; i < 4; i++)
        #pragma unroll
        for (int j = 0; j < 4; j++)
            #pragma unroll
            for (int r = 0; r < 4; r++) acc[i][j][r] = 0.f;

    for (int k0 = 0; k0 < K; k0 += GBK) {
        // load A tile [128, 32] halves (uint4 = 8 halves per thread-iter)
        #pragma unroll
        for (int it = 0; it < 2; it++) {
            int id = tid + it * 256;
            int r = id >> 2, c8 = (id & 3) << 3;
            int grow = blockRow + r;
            uint4 v = make_uint4(0u, 0u, 0u, 0u);
            if (grow < M) v = *(const uint4*)(A + (size_t)grow * K + k0 + c8);
            *(uint4*)(As + r * GSTRIDE + c8) = v;
        }
        // load B tile [128, 32] halves from Bt rows blockCol..blockCol+127
        #pragma unroll
        for (int it = 0; it < 2; it++) {
            int id = tid + it * 256;
            int r = id >> 2, c8 = (id & 3) << 3;
            uint4 v = *(const uint4*)(Bt + (size_t)(blockCol + r) * K + k0 + c8);
            *(uint4*)(Bs + r * GSTRIDE + c8) = v;
        }
        __syncthreads();

        #pragma unroll
        for (int k16 = 0; k16 < GBK; k16 += 16) {
            // A fragments for 4 m-tiles
            uint32_t af[4][4];
            #pragma unroll
            for (int mt = 0; mt < 4; mt++) {
                int rbase = warp_m * 64 + mt * 16;
                const __half* p0 = As + (rbase + gid) * GSTRIDE + k16 + tig * 2;
                const __half* p1 = As + (rbase + gid + 8) * GSTRIDE + k16 + tig * 2;
                af[mt][0] = *(const uint32_t*)p0;
                af[mt][1] = *(const uint32_t*)p1;
                af[mt][2] = *(const uint32_t*)(p0 + 8);
                af[mt][3] = *(const uint32_t*)(p1 + 8);
            }
            // B fragments for 4 n-tiles
            uint32_t bf[4][2];
            #pragma unroll
            for (int nt = 0; nt < 4; nt++) {
                int nrow = warp_n * 32 + nt * 8 + gid;
                const __half* p = Bs + nrow * GSTRIDE + k16 + tig * 2;
                bf[nt][0] = *(const uint32_t*)p;
                bf[nt][1] = *(const uint32_t*)(p + 8);
            }
            #pragma unroll
            for (int mt = 0; mt < 4; mt++)
                #pragma unroll
                for (int nt = 0; nt < 4; nt++) {
                    asm volatile(
                        "mma.sync.aligned.m16n8k16.row.col.f32.f16.f16.f32 "
                        "{%0,%1,%2,%3}, {%4,%5,%6,%7}, {%8,%9}, {%0,%1,%2,%3};"
                        : "+f"(acc[mt][nt][0]), "+f"(acc[mt][nt][1]),
                          "+f"(acc[mt][nt][2]), "+f"(acc[mt][nt][3])
                        : "r"(af[mt][0]), "r"(af[mt][1]), "r"(af[mt][2]), "r"(af[mt][3]),
                          "r"(bf[nt][0]), "r"(bf[nt][1]));
                }
        }
        __syncthreads();
    }

    // epilogue
    #pragma unroll
    for (int mt = 0; mt < 4; mt++) {
        #pragma unroll
        for (int half = 0; half < 2; half++) {
            int row = blockRow + warp_m * 64 + mt * 16 + gid + half * 8;
            if (row >= M) continue;
            float rs = (mode == 1) ? rowscale[row] : 0.f;
            #pragma unroll
            for (int nt = 0; nt < 4; nt++) {
                int col = blockCol + warp_n * 32 + nt * 8 + tig * 2;
                float v0 = acc[mt][nt][half * 2 + 0];
                float v1 = acc[mt][nt][half * 2 + 1];
                if (mode == 1) {
                    v0 = fmaxf(fmaf(rs, bias[col],     v0), 0.f);
                    v1 = fmaxf(fmaf(rs, bias[col + 1], v1), 0.f);
                    *(__half2*)(outH + (size_t)row * N + col) = __floats2half2_rn(v0, v1);
                } else {
                    *(float2*)(outF + (size_t)row * N + col) = make_float2(v0, v1);
                }
            }
        }
    }
}

// ---------------- link scoring ----------------
__global__ __launch_bounds__(256)
void link_kernel(const int* __restrict__ link, const float* __restrict__ fcb,
                 float* __restrict__ out) {
    int i = blockIdx.x * 256 + threadIdx.x;
    if (i >= N_LINKS) return;
    int a = link[2 * i], b = link[2 * i + 1];
    float x = (g_zfc[a] + g_zfc[b]) * 0.5f + fcb[0];
    out[i] = 1.0f / (1.0f + __expf(-x));
}

// ---------------- launch ----------------
extern "C" void kernel_launch(void* const* d_in, const int* in_sizes, int n_in,
                              void* d_out, int out_size) {
    const float* X    = (const float*)d_in[0];
    const float* W1   = (const float*)d_in[1];
    const float* b1   = (const float*)d_in[2];
    const float* W2   = (const float*)d_in[3];
    const float* b2   = (const float*)d_in[4];
    const float* fcW  = (const float*)d_in[5];
    const float* fcb  = (const float*)d_in[6];
    const int*   incv = (const int*)d_in[7];
    const int*   ince = (const int*)d_in[8];
    const int*   link = (const int*)d_in[9];
    float* out = (float*)d_out;

    static float*  p_s   = nullptr;
    static float*  p_t   = nullptr;
    static __half* p_X2h = nullptr;
    static __half* p_hh  = nullptr;
    static __half* p_W1T = nullptr;
    static __half* p_W2T = nullptr;
    if (!p_s) {
        cudaGetSymbolAddress((void**)&p_s,   g_s);
        cudaGetSymbolAddress((void**)&p_t,   g_t);
        cudaGetSymbolAddress((void**)&p_X2h, g_X2h);
        cudaGetSymbolAddress((void**)&p_hh,  g_hh);
        cudaGetSymbolAddress((void**)&p_W1T, g_W1T);
        cudaGetSymbolAddress((void**)&p_W2T, g_W2T);
    }

    const int TPB = 256;
    int inc_blocks    = (N_INC + TPB - 1) / TPB;
    int node_blocks   = (N_NODES + TPB - 1) / TPB;
    int edge_blocks   = (N_HEDGES + 1 + TPB - 1) / TPB;
    int warp_blocks_e = (N_HEDGES * 32 + TPB - 1) / TPB;
    int warp_blocks_n = (N_NODES * 32 + TPB - 1) / TPB;
    int wt_blocks     = (C1 * C2 + TPB - 1) / TPB;
    int gemm_rows     = (N_NODES + 127) / 128;   // 782

    // 1. node degrees + offsets
    zero_counts_kernel<<<node_blocks, TPB>>>();
    count_kernel<<<inc_blocks, TPB>>>(incv);
    node_scan_phase1<<<SCAN_BLOCKS, TPB>>>();
    node_scan_phase2<<<1, 128>>>();
    node_scan_phase3<<<SCAN_BLOCKS, TPB>>>();

    // 2. edge offsets via binary search on sorted inc_e
    edge_off_kernel<<<edge_blocks, TPB>>>(ince);

    // 3. node CSR + weight transposes (independent)
    build_csr_kernel<<<inc_blocks, TPB>>>(incv, ince);
    wt_kernel<<<wt_blocks, TPB>>>(W1, p_W1T, C1, C2);   // W1T [256,128]
    wt_kernel<<<wt_blocks, TPB>>>(W2, p_W2T, C2, C1);   // W2T [128,256]

    // 4. s = S * 1
    te_kernel<<<node_blocks, TPB>>>(incv);
    s_kernel<<<node_blocks, TPB>>>();

    // 5. X2 = S * X (fp16 output)
    edge_agg_kernel<<<warp_blocks_e, TPB>>>(X, incv);
    node_agg_h_kernel<<<warp_blocks_n, TPB>>>(p_X2h);

    // 6. h = relu(X2 @ W1 + s*b1) [N,256] fp16  (mma.sync)
    {
        dim3 grid(gemm_rows, C2 / 128);
        gemm_mma_kernel<<<grid, 256>>>(p_X2h, p_W1T, N_NODES, C1, C2, 1, p_s, b1, p_hh, nullptr);
    }

    // 7. t = h @ W2 [N,128] fp32  (mma.sync)
    {
        dim3 grid(gemm_rows, C1 / 128);
        gemm_mma_kernel<<<grid, 256>>>(p_hh, p_W2T, N_NODES, C2, C1, 0, nullptr, nullptr, nullptr, p_t);
    }

    // 8. smooth t, fused relu(+s*b2) dot fcW -> zfc
    edge_agg_kernel<<<warp_blocks_e, TPB>>>(p_t, incv);
    node_agg_final_kernel<<<warp_blocks_n, TPB>>>(b2, fcW);

    // 9. link scores
    link_kernel<<<(N_LINKS + TPB - 1) / TPB, TPB>>>(link, fcb, out);
    (void)in_sizes; (void)n_in; (void)out_size;
}

// round 5
// speedup vs baseline: 3.3445x; 1.1087x over previous
#include <cuda_runtime.h>
#include <cuda_fp16.h>
#include <math.h>
#include <stdint.h>

#define N_NODES  100000
#define N_HEDGES 100000
#define N_INC    3200000
#define N_LINKS  262144
#define C1 128
#define C2 256

#define SCAN_ELEMS 1024
#define SCAN_BLOCKS ((N_NODES + SCAN_ELEMS - 1) / SCAN_ELEMS)   // 98

// ---------------- device scratch (static; no cudaMalloc) ----------------
__device__ int   g_dv_cnt[N_NODES];
__device__ int   g_node_off[N_NODES + 1];
__device__ int   g_edge_off[N_HEDGES + 1];
__device__ int   g_cursor[N_NODES];
__device__ int   g_node_edges[N_INC];
__device__ int   g_blk_sums[SCAN_BLOCKS];
__device__ int   g_blk_offs[SCAN_BLOCKS];
__device__ float g_dvi[N_NODES];    // Dv^{-1/2}
__device__ float g_dei[N_HEDGES];   // De^{-1}
__device__ float g_te[N_HEDGES];
__device__ float g_s[N_NODES];      // s = S*1
__device__ float g_zfc[N_NODES];
__device__ __half g_Xh [(size_t)N_NODES * C1];   // X as fp16 (gather input 1)
__device__ __half g_X2h[(size_t)N_NODES * C1];   // S*X (fp16, GEMM1 input)
__device__ __half g_hh [(size_t)N_NODES * C2];   // h (fp16, GEMM2 input)
__device__ __half g_th [(size_t)N_NODES * C1];   // h W2 (fp16, gather input 2)
__device__ __half g_W1T[(size_t)C2 * C1];        // W1^T fp16 [256,128]
__device__ __half g_W2T[(size_t)C1 * C2];        // W2^T fp16 [128,256]
__device__ __half g_Yeh[(size_t)N_HEDGES * C1];  // per-edge aggregate scratch fp16

// ---------------- setup kernels ----------------
__global__ __launch_bounds__(256)
void zero_counts_kernel() {
    int i = blockIdx.x * 256 + threadIdx.x;
    if (i < N_NODES) { g_dv_cnt[i] = 0; g_cursor[i] = 0; }
}

__global__ __launch_bounds__(256)
void count_kernel(const int* __restrict__ inc_v) {
    int i = blockIdx.x * 256 + threadIdx.x;
    if (i < N_INC) atomicAdd(&g_dv_cnt[inc_v[i]], 1);
}

__global__ __launch_bounds__(256)
void node_scan_phase1() {
    int b = blockIdx.x, t = threadIdx.x;
    int base = b * SCAN_ELEMS + t * 4;
    int s = 0;
    #pragma unroll
    for (int k = 0; k < 4; k++) { int i = base + k; if (i < N_NODES) s += g_dv_cnt[i]; }
    __shared__ int sh[256];
    sh[t] = s; __syncthreads();
    #pragma unroll
    for (int d = 128; d > 0; d >>= 1) { if (t < d) sh[t] += sh[t + d]; __syncthreads(); }
    if (t == 0) g_blk_sums[b] = sh[0];
}

__global__ __launch_bounds__(128)
void node_scan_phase2() {
    int t = threadIdx.x;
    __shared__ int sh[128];
    int v = (t < SCAN_BLOCKS) ? g_blk_sums[t] : 0;
    sh[t] = v; __syncthreads();
    #pragma unroll
    for (int d = 1; d < 128; d <<= 1) {
        int x = (t >= d) ? sh[t - d] : 0; __syncthreads(); sh[t] += x; __syncthreads();
    }
    if (t < SCAN_BLOCKS) g_blk_offs[t] = sh[t] - v;
    if (t == 127) g_node_off[N_NODES] = sh[127];
}

__global__ __launch_bounds__(256)
void node_scan_phase3() {
    int b = blockIdx.x, t = threadIdx.x;
    int base = b * SCAN_ELEMS + t * 4;
    int c[4]; int s = 0;
    #pragma unroll
    for (int k = 0; k < 4; k++) { int i = base + k; c[k] = (i < N_NODES) ? g_dv_cnt[i] : 0; s += c[k]; }
    __shared__ int sh[256];
    sh[t] = s; __syncthreads();
    #pragma unroll
    for (int d = 1; d < 256; d <<= 1) {
        int x = (t >= d) ? sh[t - d] : 0; __syncthreads(); sh[t] += x; __syncthreads();
    }
    int run = g_blk_offs[b] + sh[t] - s;
    #pragma unroll
    for (int k = 0; k < 4; k++) {
        int i = base + k;
        if (i < N_NODES) {
            g_node_off[i] = run; run += c[k];
            g_dvi[i] = (c[k] > 0) ? rsqrtf((float)c[k]) : 0.0f;
        }
    }
}

__global__ __launch_bounds__(256)
void edge_off_kernel(const int* __restrict__ inc_e) {
    int e = blockIdx.x * 256 + threadIdx.x;
    if (e > N_HEDGES) return;
    int lo = 0, hi = N_INC;
    while (lo < hi) { int mid = (lo + hi) >> 1; if (inc_e[mid] < e) lo = mid + 1; else hi = mid; }
    g_edge_off[e] = lo;
}

__global__ __launch_bounds__(256)
void build_csr_kernel(const int* __restrict__ inc_v, const int* __restrict__ inc_e) {
    int i = blockIdx.x * 256 + threadIdx.x;
    if (i < N_INC) {
        int v = inc_v[i];
        int pos = g_node_off[v] + atomicAdd(&g_cursor[v], 1);
        g_node_edges[pos] = inc_e[i];
    }
}

__global__ __launch_bounds__(256)
void te_kernel(const int* __restrict__ inc_v) {
    int e = blockIdx.x * 256 + threadIdx.x;
    if (e >= N_HEDGES) return;
    int b = g_edge_off[e], en = g_edge_off[e + 1];
    float sum = 0.0f;
    for (int i = b; i < en; i++) sum += g_dvi[inc_v[i]];
    float dei = (en > b) ? 1.0f / (float)(en - b) : 0.0f;
    g_dei[e] = dei;
    g_te[e] = dei * sum;
}

__global__ __launch_bounds__(256)
void s_kernel() {
    int v = blockIdx.x * 256 + threadIdx.x;
    if (v >= N_NODES) return;
    int b = g_node_off[v], en = g_node_off[v + 1];
    float sum = 0.0f;
    for (int j = b; j < en; j++) sum += g_te[g_node_edges[j]];
    g_s[v] = g_dvi[v] * sum;
}

// weight transpose + fp16: out[n*K + k] = W[k*N + n]
__global__ __launch_bounds__(256)
void wt_kernel(const float* __restrict__ W, __half* __restrict__ out, int K, int N) {
    int i = blockIdx.x * 256 + threadIdx.x;
    if (i < K * N) {
        int n = i / K, k = i % K;
        out[i] = __float2half(W[k * N + n]);
    }
}

// X fp32 -> fp16
__global__ __launch_bounds__(256)
void x_to_h_kernel(const float* __restrict__ X, __half* __restrict__ Xh) {
    int i = blockIdx.x * 256 + threadIdx.x;          // half2 index
    int n = (N_NODES * C1) >> 1;
    if (i < n) {
        float2 v = *(const float2*)(X + i * 2);
        *((__half2*)Xh + i) = __floats2half2_rn(v.x, v.y);
    }
}

// ---------------- fp16 smoothing (C=128), one warp per edge/node ----------------
// Ye[e,:] = de_inv[e] * sum dvi[u] * Xin[u,:]   (fp16 rows, fp32 accum)
__global__ __launch_bounds__(256)
void edge_agg_h_kernel(const __half* __restrict__ Xin, const int* __restrict__ inc_v) {
    int w = (blockIdx.x * 256 + threadIdx.x) >> 5;
    int lane = threadIdx.x & 31;
    if (w >= N_HEDGES) return;
    int b = g_edge_off[w], e = g_edge_off[w + 1];
    float4 acc = make_float4(0.f, 0.f, 0.f, 0.f);
    int i = b;
    for (; i + 4 <= e; i += 4) {
        int u0 = inc_v[i], u1 = inc_v[i + 1], u2 = inc_v[i + 2], u3 = inc_v[i + 3];
        float w0 = g_dvi[u0], w1 = g_dvi[u1], w2 = g_dvi[u2], w3 = g_dvi[u3];
        uint2 x0 = *(const uint2*)(Xin + (size_t)u0 * C1 + lane * 4);
        uint2 x1 = *(const uint2*)(Xin + (size_t)u1 * C1 + lane * 4);
        uint2 x2 = *(const uint2*)(Xin + (size_t)u2 * C1 + lane * 4);
        uint2 x3 = *(const uint2*)(Xin + (size_t)u3 * C1 + lane * 4);
        float2 a0 = __half22float2(*(__half2*)&x0.x), b0 = __half22float2(*(__half2*)&x0.y);
        float2 a1 = __half22float2(*(__half2*)&x1.x), b1 = __half22float2(*(__half2*)&x1.y);
        float2 a2 = __half22float2(*(__half2*)&x2.x), b2 = __half22float2(*(__half2*)&x2.y);
        float2 a3 = __half22float2(*(__half2*)&x3.x), b3 = __half22float2(*(__half2*)&x3.y);
        acc.x = fmaf(w0, a0.x, acc.x); acc.y = fmaf(w0, a0.y, acc.y);
        acc.z = fmaf(w0, b0.x, acc.z); acc.w = fmaf(w0, b0.y, acc.w);
        acc.x = fmaf(w1, a1.x, acc.x); acc.y = fmaf(w1, a1.y, acc.y);
        acc.z = fmaf(w1, b1.x, acc.z); acc.w = fmaf(w1, b1.y, acc.w);
        acc.x = fmaf(w2, a2.x, acc.x); acc.y = fmaf(w2, a2.y, acc.y);
        acc.z = fmaf(w2, b2.x, acc.z); acc.w = fmaf(w2, b2.y, acc.w);
        acc.x = fmaf(w3, a3.x, acc.x); acc.y = fmaf(w3, a3.y, acc.y);
        acc.z = fmaf(w3, b3.x, acc.z); acc.w = fmaf(w3, b3.y, acc.w);
    }
    for (; i < e; i++) {
        int u = inc_v[i];
        float wu = g_dvi[u];
        uint2 x = *(const uint2*)(Xin + (size_t)u * C1 + lane * 4);
        float2 a = __half22float2(*(__half2*)&x.x), c = __half22float2(*(__half2*)&x.y);
        acc.x = fmaf(wu, a.x, acc.x); acc.y = fmaf(wu, a.y, acc.y);
        acc.z = fmaf(wu, c.x, acc.z); acc.w = fmaf(wu, c.y, acc.w);
    }
    float d = g_dei[w];
    __half2* dst = (__half2*)(g_Yeh + (size_t)w * C1 + lane * 4);
    dst[0] = __floats2half2_rn(acc.x * d, acc.y * d);
    dst[1] = __floats2half2_rn(acc.z * d, acc.w * d);
}

// node aggregation over fp16 Ye -> fp16 output
__global__ __launch_bounds__(256)
void node_agg_h_kernel(__half* __restrict__ Xout) {
    int v = (blockIdx.x * 256 + threadIdx.x) >> 5;
    int lane = threadIdx.x & 31;
    if (v >= N_NODES) return;
    int b = g_node_off[v], e = g_node_off[v + 1];
    float4 acc = make_float4(0.f, 0.f, 0.f, 0.f);
    int j = b;
    for (; j + 4 <= e; j += 4) {
        int e0 = g_node_edges[j], e1 = g_node_edges[j + 1];
        int e2 = g_node_edges[j + 2], e3 = g_node_edges[j + 3];
        uint2 y0 = *(const uint2*)(g_Yeh + (size_t)e0 * C1 + lane * 4);
        uint2 y1 = *(const uint2*)(g_Yeh + (size_t)e1 * C1 + lane * 4);
        uint2 y2 = *(const uint2*)(g_Yeh + (size_t)e2 * C1 + lane * 4);
        uint2 y3 = *(const uint2*)(g_Yeh + (size_t)e3 * C1 + lane * 4);
        float2 a0 = __half22float2(*(__half2*)&y0.x), b0 = __half22float2(*(__half2*)&y0.y);
        float2 a1 = __half22float2(*(__half2*)&y1.x), b1 = __half22float2(*(__half2*)&y1.y);
        float2 a2 = __half22float2(*(__half2*)&y2.x), b2 = __half22float2(*(__half2*)&y2.y);
        float2 a3 = __half22float2(*(__half2*)&y3.x), b3 = __half22float2(*(__half2*)&y3.y);
        acc.x += a0.x + a1.x + a2.x + a3.x;
        acc.y += a0.y + a1.y + a2.y + a3.y;
        acc.z += b0.x + b1.x + b2.x + b3.x;
        acc.w += b0.y + b1.y + b2.y + b3.y;
    }
    for (; j < e; j++) {
        int ee = g_node_edges[j];
        uint2 y = *(const uint2*)(g_Yeh + (size_t)ee * C1 + lane * 4);
        float2 a = __half22float2(*(__half2*)&y.x), c = __half22float2(*(__half2*)&y.y);
        acc.x += a.x; acc.y += a.y; acc.z += c.x; acc.w += c.y;
    }
    float d = g_dvi[v];
    __half2* dst = (__half2*)(Xout + (size_t)v * C1 + lane * 4);
    dst[0] = __floats2half2_rn(acc.x * d, acc.y * d);
    dst[1] = __floats2half2_rn(acc.z * d, acc.w * d);
}

// final node pass: zfc[v] = sum_c relu(dvi[v]*agg_c + s[v]*b2[c]) * fcW[c]
__global__ __launch_bounds__(256)
void node_agg_final_kernel(const float* __restrict__ b2, const float* __restrict__ fcW) {
    int v = (blockIdx.x * 256 + threadIdx.x) >> 5;
    int lane = threadIdx.x & 31;
    if (v >= N_NODES) return;
    int b = g_node_off[v], e = g_node_off[v + 1];
    float4 acc = make_float4(0.f, 0.f, 0.f, 0.f);
    int j = b;
    for (; j + 4 <= e; j += 4) {
        int e0 = g_node_edges[j], e1 = g_node_edges[j + 1];
        int e2 = g_node_edges[j + 2], e3 = g_node_edges[j + 3];
        uint2 y0 = *(const uint2*)(g_Yeh + (size_t)e0 * C1 + lane * 4);
        uint2 y1 = *(const uint2*)(g_Yeh + (size_t)e1 * C1 + lane * 4);
        uint2 y2 = *(const uint2*)(g_Yeh + (size_t)e2 * C1 + lane * 4);
        uint2 y3 = *(const uint2*)(g_Yeh + (size_t)e3 * C1 + lane * 4);
        float2 a0 = __half22float2(*(__half2*)&y0.x), b0 = __half22float2(*(__half2*)&y0.y);
        float2 a1 = __half22float2(*(__half2*)&y1.x), b1 = __half22float2(*(__half2*)&y1.y);
        float2 a2 = __half22float2(*(__half2*)&y2.x), b2 = __half22float2(*(__half2*)&y2.y);
        float2 a3 = __half22float2(*(__half2*)&y3.x), b3 = __half22float2(*(__half2*)&y3.y);
        acc.x += a0.x + a1.x + a2.x + a3.x;
        acc.y += a0.y + a1.y + a2.y + a3.y;
        acc.z += b0.x + b1.x + b2.x + b3.x;
        acc.w += b0.y + b1.y + b2.y + b3.y;
    }
    for (; j < e; j++) {
        int ee = g_node_edges[j];
        uint2 y = *(const uint2*)(g_Yeh + (size_t)ee * C1 + lane * 4);
        float2 a = __half22float2(*(__half2*)&y.x), c = __half22float2(*(__half2*)&y.y);
        acc.x += a.x; acc.y += a.y; acc.z += c.x; acc.w += c.y;
    }
    float d  = g_dvi[v];
    float sv = g_s[v];
    float4 bb = *(const float4*)(b2 + lane * 4);
    float4 fw = *(const float4*)(fcW + lane * 4);
    float zx = fmaxf(fmaf(d, acc.x, sv * bb.x), 0.f);
    float zy = fmaxf(fmaf(d, acc.y, sv * bb.y), 0.f);
    float zz = fmaxf(fmaf(d, acc.z, sv * bb.z), 0.f);
    float zw = fmaxf(fmaf(d, acc.w, sv * bb.w), 0.f);
    float p = zx * fw.x + zy * fw.y + zz * fw.z + zw * fw.w;
    #pragma unroll
    for (int o = 16; o > 0; o >>= 1) p += __shfl_down_sync(0xffffffffu, p, o);
    if (lane == 0) g_zfc[v] = p;
}

// ---------------- mma.sync fp16 GEMM: C[M,N] = A[M,K] @ Bt[N,K]^T ----------------
// mode 1: outH = relu(C + rowscale[m]*bias[n]) as fp16
// mode 0: outH = C as fp16
#define GBK 32
#define GSTRIDE (GBK + 8)     // padded smem row stride in halves

__global__ __launch_bounds__(256)
void gemm_mma_kernel(const __half* __restrict__ A, const __half* __restrict__ Bt,
                     int M, int K, int N, int mode,
                     const float* __restrict__ rowscale, const float* __restrict__ bias,
                     __half* __restrict__ outH) {
    __shared__ __half As[128 * GSTRIDE];
    __shared__ __half Bs[128 * GSTRIDE];

    int tid = threadIdx.x;
    int wid = tid >> 5, lane = tid & 31;
    int warp_m = wid >> 2;          // 0..1  (64-row slab)
    int warp_n = wid & 3;           // 0..3  (32-col slab)
    int gid = lane >> 2;            // 0..7
    int tig = lane & 3;             // 0..3

    int blockRow = blockIdx.x * 128;
    int blockCol = blockIdx.y * 128;

    float acc[4][4][4];
    #pragma unroll
    for (int i = 0; i < 4; i++)
        #pragma unroll
        for (int j = 0; j < 4; j++)
            #pragma unroll
            for (int r = 0; r < 4; r++) acc[i][j][r] = 0.f;

    for (int k0 = 0; k0 < K; k0 += GBK) {
        #pragma unroll
        for (int it = 0; it < 2; it++) {
            int id = tid + it * 256;
            int r = id >> 2, c8 = (id & 3) << 3;
            int grow = blockRow + r;
            uint4 v = make_uint4(0u, 0u, 0u, 0u);
            if (grow < M) v = *(const uint4*)(A + (size_t)grow * K + k0 + c8);
            *(uint4*)(As + r * GSTRIDE + c8) = v;
        }
        #pragma unroll
        for (int it = 0; it < 2; it++) {
            int id = tid + it * 256;
            int r = id >> 2, c8 = (id & 3) << 3;
            uint4 v = *(const uint4*)(Bt + (size_t)(blockCol + r) * K + k0 + c8);
            *(uint4*)(Bs + r * GSTRIDE + c8) = v;
        }
        __syncthreads();

        #pragma unroll
        for (int k16 = 0; k16 < GBK; k16 += 16) {
            uint32_t af[4][4];
            #pragma unroll
            for (int mt = 0; mt < 4; mt++) {
                int rbase = warp_m * 64 + mt * 16;
                const __half* p0 = As + (rbase + gid) * GSTRIDE + k16 + tig * 2;
                const __half* p1 = As + (rbase + gid + 8) * GSTRIDE + k16 + tig * 2;
                af[mt][0] = *(const uint32_t*)p0;
                af[mt][1] = *(const uint32_t*)p1;
                af[mt][2] = *(const uint32_t*)(p0 + 8);
                af[mt][3] = *(const uint32_t*)(p1 + 8);
            }
            uint32_t bf[4][2];
            #pragma unroll
            for (int nt = 0; nt < 4; nt++) {
                int nrow = warp_n * 32 + nt * 8 + gid;
                const __half* p = Bs + nrow * GSTRIDE + k16 + tig * 2;
                bf[nt][0] = *(const uint32_t*)p;
                bf[nt][1] = *(const uint32_t*)(p + 8);
            }
            #pragma unroll
            for (int mt = 0; mt < 4; mt++)
                #pragma unroll
                for (int nt = 0; nt < 4; nt++) {
                    asm volatile(
                        "mma.sync.aligned.m16n8k16.row.col.f32.f16.f16.f32 "
                        "{%0,%1,%2,%3}, {%4,%5,%6,%7}, {%8,%9}, {%0,%1,%2,%3};"
                        : "+f"(acc[mt][nt][0]), "+f"(acc[mt][nt][1]),
                          "+f"(acc[mt][nt][2]), "+f"(acc[mt][nt][3])
                        : "r"(af[mt][0]), "r"(af[mt][1]), "r"(af[mt][2]), "r"(af[mt][3]),
                          "r"(bf[nt][0]), "r"(bf[nt][1]));
                }
        }
        __syncthreads();
    }

    #pragma unroll
    for (int mt = 0; mt < 4; mt++) {
        #pragma unroll
        for (int half = 0; half < 2; half++) {
            int row = blockRow + warp_m * 64 + mt * 16 + gid + half * 8;
            if (row >= M) continue;
            float rs = (mode == 1) ? rowscale[row] : 0.f;
            #pragma unroll
            for (int nt = 0; nt < 4; nt++) {
                int col = blockCol + warp_n * 32 + nt * 8 + tig * 2;
                float v0 = acc[mt][nt][half * 2 + 0];
                float v1 = acc[mt][nt][half * 2 + 1];
                if (mode == 1) {
                    v0 = fmaxf(fmaf(rs, bias[col],     v0), 0.f);
                    v1 = fmaxf(fmaf(rs, bias[col + 1], v1), 0.f);
                }
                *(__half2*)(outH + (size_t)row * N + col) = __floats2half2_rn(v0, v1);
            }
        }
    }
}

// ---------------- link scoring ----------------
__global__ __launch_bounds__(256)
void link_kernel(const int* __restrict__ link, const float* __restrict__ fcb,
                 float* __restrict__ out) {
    int i = blockIdx.x * 256 + threadIdx.x;
    if (i >= N_LINKS) return;
    int a = link[2 * i], b = link[2 * i + 1];
    float x = (g_zfc[a] + g_zfc[b]) * 0.5f + fcb[0];
    out[i] = 1.0f / (1.0f + __expf(-x));
}

// ---------------- launch ----------------
extern "C" void kernel_launch(void* const* d_in, const int* in_sizes, int n_in,
                              void* d_out, int out_size) {
    const float* X    = (const float*)d_in[0];
    const float* W1   = (const float*)d_in[1];
    const float* b1   = (const float*)d_in[2];
    const float* W2   = (const float*)d_in[3];
    const float* b2   = (const float*)d_in[4];
    const float* fcW  = (const float*)d_in[5];
    const float* fcb  = (const float*)d_in[6];
    const int*   incv = (const int*)d_in[7];
    const int*   ince = (const int*)d_in[8];
    const int*   link = (const int*)d_in[9];
    float* out = (float*)d_out;

    static float*  p_s   = nullptr;
    static __half* p_Xh  = nullptr;
    static __half* p_X2h = nullptr;
    static __half* p_hh  = nullptr;
    static __half* p_th  = nullptr;
    static __half* p_W1T = nullptr;
    static __half* p_W2T = nullptr;
    if (!p_s) {
        cudaGetSymbolAddress((void**)&p_s,   g_s);
        cudaGetSymbolAddress((void**)&p_Xh,  g_Xh);
        cudaGetSymbolAddress((void**)&p_X2h, g_X2h);
        cudaGetSymbolAddress((void**)&p_hh,  g_hh);
        cudaGetSymbolAddress((void**)&p_th,  g_th);
        cudaGetSymbolAddress((void**)&p_W1T, g_W1T);
        cudaGetSymbolAddress((void**)&p_W2T, g_W2T);
    }

    const int TPB = 256;
    int inc_blocks    = (N_INC + TPB - 1) / TPB;
    int node_blocks   = (N_NODES + TPB - 1) / TPB;
    int edge_blocks   = (N_HEDGES + 1 + TPB - 1) / TPB;
    int warp_blocks_e = (N_HEDGES * 32 + TPB - 1) / TPB;
    int warp_blocks_n = (N_NODES * 32 + TPB - 1) / TPB;
    int wt_blocks     = (C1 * C2 + TPB - 1) / TPB;
    int xh_blocks     = ((N_NODES * C1 / 2) + TPB - 1) / TPB;
    int gemm_rows     = (N_NODES + 127) / 128;   // 782

    // 1. node degrees + offsets
    zero_counts_kernel<<<node_blocks, TPB>>>();
    count_kernel<<<inc_blocks, TPB>>>(incv);
    node_scan_phase1<<<SCAN_BLOCKS, TPB>>>();
    node_scan_phase2<<<1, 128>>>();
    node_scan_phase3<<<SCAN_BLOCKS, TPB>>>();

    // 2. edge offsets via binary search on sorted inc_e; X -> fp16 (independent)
    edge_off_kernel<<<edge_blocks, TPB>>>(ince);
    x_to_h_kernel<<<xh_blocks, TPB>>>(X, p_Xh);

    // 3. node CSR + weight transposes (independent)
    build_csr_kernel<<<inc_blocks, TPB>>>(incv, ince);
    wt_kernel<<<wt_blocks, TPB>>>(W1, p_W1T, C1, C2);   // W1T [256,128]
    wt_kernel<<<wt_blocks, TPB>>>(W2, p_W2T, C2, C1);   // W2T [128,256]

    // 4. s = S * 1
    te_kernel<<<node_blocks, TPB>>>(incv);
    s_kernel<<<node_blocks, TPB>>>();

    // 5. X2 = S * X (fp16 gathers)
    edge_agg_h_kernel<<<warp_blocks_e, TPB>>>(p_Xh, incv);
    node_agg_h_kernel<<<warp_blocks_n, TPB>>>(p_X2h);

    // 6. h = relu(X2 @ W1 + s*b1) [N,256] fp16  (mma.sync)
    {
        dim3 grid(gemm_rows, C2 / 128);
        gemm_mma_kernel<<<grid, 256>>>(p_X2h, p_W1T, N_NODES, C1, C2, 1, p_s, b1, p_hh);
    }

    // 7. t = h @ W2 [N,128] fp16  (mma.sync)
    {
        dim3 grid(gemm_rows, C1 / 128);
        gemm_mma_kernel<<<grid, 256>>>(p_hh, p_W2T, N_NODES, C2, C1, 0, nullptr, nullptr, p_th);
    }

    // 8. smooth t, fused relu(+s*b2) dot fcW -> zfc
    edge_agg_h_kernel<<<warp_blocks_e, TPB>>>(p_th, incv);
    node_agg_final_kernel<<<warp_blocks_n, TPB>>>(b2, fcW);

    // 9. link scores
    link_kernel<<<(N_LINKS + TPB - 1) / TPB, TPB>>>(link, fcb, out);
    (void)in_sizes; (void)n_in; (void)out_size;
}

// round 6
// speedup vs baseline: 3.6178x; 1.0817x over previous
#include <cuda_runtime.h>
#include <cuda_fp16.h>
#include <math.h>
#include <stdint.h>

#define N_NODES  100000
#define N_HEDGES 100000
#define N_INC    3200000
#define N_LINKS  262144
#define C1 128
#define C2 256

#define SCAN_ELEMS 1024
#define SCAN_BLOCKS ((N_NODES + SCAN_ELEMS - 1) / SCAN_ELEMS)   // 98

// ---------------- device scratch (static; no cudaMalloc) ----------------
__device__ int   g_dv_cnt[N_NODES];
__device__ int   g_node_off[N_NODES + 1];
__device__ int   g_edge_off[N_HEDGES + 1];
__device__ int   g_cursor[N_NODES];
__device__ int   g_node_edges[N_INC];
__device__ int   g_blk_sums[SCAN_BLOCKS];
__device__ int   g_blk_offs[SCAN_BLOCKS];
__device__ float g_dvi[N_NODES];    // Dv^{-1/2}
__device__ float g_te[N_HEDGES];
__device__ float g_s[N_NODES];      // s = S*1
__device__ float g_zfc[N_NODES];
__device__ __half g_Xh [(size_t)N_NODES * C1];   // X as fp16
__device__ __half g_X2h[(size_t)N_NODES * C1];   // S*X (fp16, GEMM1 input)
__device__ __half g_hh [(size_t)N_NODES * C2];   // h (fp16, GEMM2 input)
__device__ __half g_th [(size_t)N_NODES * C1];   // h W2 (fp16)
__device__ __half g_W1T[(size_t)C2 * C1];        // W1^T fp16 [256,128]
__device__ __half g_W2T[(size_t)C1 * C2];        // W2^T fp16 [128,256]
__device__ __half g_Yeh[(size_t)N_HEDGES * C1];  // per-edge aggregate scratch fp16

// ---------------- setup kernels ----------------
__global__ __launch_bounds__(256)
void zero_counts_kernel() {
    int i = blockIdx.x * 256 + threadIdx.x;
    if (i < N_NODES) { g_dv_cnt[i] = 0; g_cursor[i] = 0; }
}

__global__ __launch_bounds__(256)
void count_kernel(const int* __restrict__ inc_v) {
    int i = blockIdx.x * 256 + threadIdx.x;
    if (i < N_INC) atomicAdd(&g_dv_cnt[inc_v[i]], 1);
}

__global__ __launch_bounds__(256)
void node_scan_phase1() {
    int b = blockIdx.x, t = threadIdx.x;
    int base = b * SCAN_ELEMS + t * 4;
    int s = 0;
    #pragma unroll
    for (int k = 0; k < 4; k++) { int i = base + k; if (i < N_NODES) s += g_dv_cnt[i]; }
    __shared__ int sh[256];
    sh[t] = s; __syncthreads();
    #pragma unroll
    for (int d = 128; d > 0; d >>= 1) { if (t < d) sh[t] += sh[t + d]; __syncthreads(); }
    if (t == 0) g_blk_sums[b] = sh[0];
}

__global__ __launch_bounds__(128)
void node_scan_phase2() {
    int t = threadIdx.x;
    __shared__ int sh[128];
    int v = (t < SCAN_BLOCKS) ? g_blk_sums[t] : 0;
    sh[t] = v; __syncthreads();
    #pragma unroll
    for (int d = 1; d < 128; d <<= 1) {
        int x = (t >= d) ? sh[t - d] : 0; __syncthreads(); sh[t] += x; __syncthreads();
    }
    if (t < SCAN_BLOCKS) g_blk_offs[t] = sh[t] - v;
    if (t == 127) g_node_off[N_NODES] = sh[127];
}

__global__ __launch_bounds__(256)
void node_scan_phase3() {
    int b = blockIdx.x, t = threadIdx.x;
    int base = b * SCAN_ELEMS + t * 4;
    int c[4]; int s = 0;
    #pragma unroll
    for (int k = 0; k < 4; k++) { int i = base + k; c[k] = (i < N_NODES) ? g_dv_cnt[i] : 0; s += c[k]; }
    __shared__ int sh[256];
    sh[t] = s; __syncthreads();
    #pragma unroll
    for (int d = 1; d < 256; d <<= 1) {
        int x = (t >= d) ? sh[t - d] : 0; __syncthreads(); sh[t] += x; __syncthreads();
    }
    int run = g_blk_offs[b] + sh[t] - s;
    #pragma unroll
    for (int k = 0; k < 4; k++) {
        int i = base + k;
        if (i < N_NODES) {
            g_node_off[i] = run; run += c[k];
            g_dvi[i] = (c[k] > 0) ? rsqrtf((float)c[k]) : 0.0f;
        }
    }
}

__global__ __launch_bounds__(256)
void edge_off_kernel(const int* __restrict__ inc_e) {
    int e = blockIdx.x * 256 + threadIdx.x;
    if (e > N_HEDGES) return;
    int lo = 0, hi = N_INC;
    while (lo < hi) { int mid = (lo + hi) >> 1; if (inc_e[mid] < e) lo = mid + 1; else hi = mid; }
    g_edge_off[e] = lo;
}

__global__ __launch_bounds__(256)
void build_csr_kernel(const int* __restrict__ inc_v, const int* __restrict__ inc_e) {
    int i = blockIdx.x * 256 + threadIdx.x;
    if (i < N_INC) {
        int v = inc_v[i];
        int pos = g_node_off[v] + atomicAdd(&g_cursor[v], 1);
        g_node_edges[pos] = inc_e[i];
    }
}

__global__ __launch_bounds__(256)
void te_kernel(const int* __restrict__ inc_v) {
    int e = blockIdx.x * 256 + threadIdx.x;
    if (e >= N_HEDGES) return;
    int b = g_edge_off[e], en = g_edge_off[e + 1];
    float sum = 0.0f;
    for (int i = b; i < en; i++) sum += g_dvi[inc_v[i]];
    float dei = (en > b) ? 1.0f / (float)(en - b) : 0.0f;
    g_te[e] = dei * sum;
}

__global__ __launch_bounds__(256)
void s_kernel() {
    int v = blockIdx.x * 256 + threadIdx.x;
    if (v >= N_NODES) return;
    int b = g_node_off[v], en = g_node_off[v + 1];
    float sum = 0.0f;
    for (int j = b; j < en; j++) sum += g_te[g_node_edges[j]];
    g_s[v] = g_dvi[v] * sum;
}

// weight transpose + fp16: out[n*K + k] = W[k*N + n]
__global__ __launch_bounds__(256)
void wt_kernel(const float* __restrict__ W, __half* __restrict__ out, int K, int N) {
    int i = blockIdx.x * 256 + threadIdx.x;
    if (i < K * N) {
        int n = i / K, k = i % K;
        out[i] = __float2half(W[k * N + n]);
    }
}

// X fp32 -> fp16
__global__ __launch_bounds__(256)
void x_to_h_kernel(const float* __restrict__ X, __half* __restrict__ Xh) {
    int i = blockIdx.x * 256 + threadIdx.x;          // half2 index
    int n = (N_NODES * C1) >> 1;
    if (i < n) {
        float2 v = *(const float2*)(X + i * 2);
        *((__half2*)Xh + i) = __floats2half2_rn(v.x, v.y);
    }
}

// ---------------- gathers: one warp per edge/node, 2 incidences per iter ----------------
// lane layout: half = lane>>4 (processes incidences b+half, b+half+2, ...),
//              li = lane&15  (channels li*8 .. li*8+7, 16 B = uint4 of 8 halves)
__device__ __forceinline__ void accum_row_h8(float* a, const __half* __restrict__ row,
                                             int li, float wu) {
    uint4 x = *(const uint4*)(row + li * 8);
    const __half2* hx = (const __half2*)&x;
    float2 f0 = __half22float2(hx[0]);
    float2 f1 = __half22float2(hx[1]);
    float2 f2 = __half22float2(hx[2]);
    float2 f3 = __half22float2(hx[3]);
    a[0] = fmaf(wu, f0.x, a[0]); a[1] = fmaf(wu, f0.y, a[1]);
    a[2] = fmaf(wu, f1.x, a[2]); a[3] = fmaf(wu, f1.y, a[3]);
    a[4] = fmaf(wu, f2.x, a[4]); a[5] = fmaf(wu, f2.y, a[5]);
    a[6] = fmaf(wu, f3.x, a[6]); a[7] = fmaf(wu, f3.y, a[7]);
}

// Ye[e,:] = (1/deg_e) * sum dvi[u] * Xin[u,:]
__global__ __launch_bounds__(256)
void edge_agg_h_kernel(const __half* __restrict__ Xin, const int* __restrict__ inc_v) {
    int w = (blockIdx.x * 256 + threadIdx.x) >> 5;
    if (w >= N_HEDGES) return;
    int lane = threadIdx.x & 31;
    int half = lane >> 4, li = lane & 15;
    int b = g_edge_off[w], e = g_edge_off[w + 1];
    float a[8] = {0.f, 0.f, 0.f, 0.f, 0.f, 0.f, 0.f, 0.f};

    int i = b + half;
    for (; i + 2 < e; i += 4) {
        int u0 = inc_v[i], u1 = inc_v[i + 2];
        float w0 = g_dvi[u0], w1 = g_dvi[u1];
        accum_row_h8(a, Xin + (size_t)u0 * C1, li, w0);
        accum_row_h8(a, Xin + (size_t)u1 * C1, li, w1);
    }
    if (i < e) {
        int u = inc_v[i];
        accum_row_h8(a, Xin + (size_t)u * C1, li, g_dvi[u]);
    }
    // combine halves: lanes 16-31 -> lanes 0-15
    #pragma unroll
    for (int r = 0; r < 8; r++) a[r] += __shfl_down_sync(0xffffffffu, a[r], 16);
    if (half == 0) {
        float d = (e > b) ? 1.0f / (float)(e - b) : 0.0f;
        uint4 o;
        ((__half2*)&o)[0] = __floats2half2_rn(a[0] * d, a[1] * d);
        ((__half2*)&o)[1] = __floats2half2_rn(a[2] * d, a[3] * d);
        ((__half2*)&o)[2] = __floats2half2_rn(a[4] * d, a[5] * d);
        ((__half2*)&o)[3] = __floats2half2_rn(a[6] * d, a[7] * d);
        *(uint4*)(g_Yeh + (size_t)w * C1 + li * 8) = o;
    }
}

// Xout[v,:] = dvi[v] * sum_e Ye[e,:]
__global__ __launch_bounds__(256)
void node_agg_h_kernel(__half* __restrict__ Xout) {
    int v = (blockIdx.x * 256 + threadIdx.x) >> 5;
    if (v >= N_NODES) return;
    int lane = threadIdx.x & 31;
    int half = lane >> 4, li = lane & 15;
    int b = g_node_off[v], e = g_node_off[v + 1];
    float a[8] = {0.f, 0.f, 0.f, 0.f, 0.f, 0.f, 0.f, 0.f};

    int j = b + half;
    for (; j + 2 < e; j += 4) {
        int e0 = g_node_edges[j], e1 = g_node_edges[j + 2];
        accum_row_h8(a, g_Yeh + (size_t)e0 * C1, li, 1.0f);
        accum_row_h8(a, g_Yeh + (size_t)e1 * C1, li, 1.0f);
    }
    if (j < e) {
        int ee = g_node_edges[j];
        accum_row_h8(a, g_Yeh + (size_t)ee * C1, li, 1.0f);
    }
    #pragma unroll
    for (int r = 0; r < 8; r++) a[r] += __shfl_down_sync(0xffffffffu, a[r], 16);
    if (half == 0) {
        float d = g_dvi[v];
        uint4 o;
        ((__half2*)&o)[0] = __floats2half2_rn(a[0] * d, a[1] * d);
        ((__half2*)&o)[1] = __floats2half2_rn(a[2] * d, a[3] * d);
        ((__half2*)&o)[2] = __floats2half2_rn(a[4] * d, a[5] * d);
        ((__half2*)&o)[3] = __floats2half2_rn(a[6] * d, a[7] * d);
        *(uint4*)(Xout + (size_t)v * C1 + li * 8) = o;
    }
}

// final: zfc[v] = sum_c relu(dvi[v]*agg_c + s[v]*b2[c]) * fcW[c]
__global__ __launch_bounds__(256)
void node_agg_final_kernel(const float* __restrict__ b2, const float* __restrict__ fcW) {
    int v = (blockIdx.x * 256 + threadIdx.x) >> 5;
    if (v >= N_NODES) return;
    int lane = threadIdx.x & 31;
    int half = lane >> 4, li = lane & 15;
    int b = g_node_off[v], e = g_node_off[v + 1];
    float a[8] = {0.f, 0.f, 0.f, 0.f, 0.f, 0.f, 0.f, 0.f};

    int j = b + half;
    for (; j + 2 < e; j += 4) {
        int e0 = g_node_edges[j], e1 = g_node_edges[j + 2];
        accum_row_h8(a, g_Yeh + (size_t)e0 * C1, li, 1.0f);
        accum_row_h8(a, g_Yeh + (size_t)e1 * C1, li, 1.0f);
    }
    if (j < e) {
        int ee = g_node_edges[j];
        accum_row_h8(a, g_Yeh + (size_t)ee * C1, li, 1.0f);
    }
    #pragma unroll
    for (int r = 0; r < 8; r++) a[r] += __shfl_down_sync(0xffffffffu, a[r], 16);

    float p = 0.0f;
    if (half == 0) {
        float d  = g_dvi[v];
        float sv = g_s[v];
        float4 bb0 = *(const float4*)(b2 + li * 8);
        float4 bb1 = *(const float4*)(b2 + li * 8 + 4);
        float4 fw0 = *(const float4*)(fcW + li * 8);
        float4 fw1 = *(const float4*)(fcW + li * 8 + 4);
        p += fmaxf(fmaf(d, a[0], sv * bb0.x), 0.f) * fw0.x;
        p += fmaxf(fmaf(d, a[1], sv * bb0.y), 0.f) * fw0.y;
        p += fmaxf(fmaf(d, a[2], sv * bb0.z), 0.f) * fw0.z;
        p += fmaxf(fmaf(d, a[3], sv * bb0.w), 0.f) * fw0.w;
        p += fmaxf(fmaf(d, a[4], sv * bb1.x), 0.f) * fw1.x;
        p += fmaxf(fmaf(d, a[5], sv * bb1.y), 0.f) * fw1.y;
        p += fmaxf(fmaf(d, a[6], sv * bb1.z), 0.f) * fw1.z;
        p += fmaxf(fmaf(d, a[7], sv * bb1.w), 0.f) * fw1.w;
    }
    #pragma unroll
    for (int o = 8; o > 0; o >>= 1) p += __shfl_down_sync(0xffffffffu, p, o);
    if (lane == 0) g_zfc[v] = p;
}

// ---------------- mma.sync fp16 GEMM: C[M,N] = A[M,K] @ Bt[N,K]^T ----------------
#define GBK 32
#define GSTRIDE (GBK + 8)

__global__ __launch_bounds__(256)
void gemm_mma_kernel(const __half* __restrict__ A, const __half* __restrict__ Bt,
                     int M, int K, int N, int mode,
                     const float* __restrict__ rowscale, const float* __restrict__ bias,
                     __half* __restrict__ outH) {
    __shared__ __half As[128 * GSTRIDE];
    __shared__ __half Bs[128 * GSTRIDE];

    int tid = threadIdx.x;
    int wid = tid >> 5, lane = tid & 31;
    int warp_m = wid >> 2;
    int warp_n = wid & 3;
    int gid = lane >> 2;
    int tig = lane & 3;

    int blockRow = blockIdx.x * 128;
    int blockCol = blockIdx.y * 128;

    float acc[4][4][4];
    #pragma unroll
    for (int i = 0; i < 4; i++)
        #pragma unroll
        for (int j = 0; j < 4; j++)
            #pragma unroll
            for (int r = 0; r < 4; r++) acc[i][j][r] = 0.f;

    for (int k0 = 0; k0 < K; k0 += GBK) {
        #pragma unroll
        for (int it = 0; it < 2; it++) {
            int id = tid + it * 256;
            int r = id >> 2, c8 = (id & 3) << 3;
            int grow = blockRow + r;
            uint4 v = make_uint4(0u, 0u, 0u, 0u);
            if (grow < M) v = *(const uint4*)(A + (size_t)grow * K + k0 + c8);
            *(uint4*)(As + r * GSTRIDE + c8) = v;
        }
        #pragma unroll
        for (int it = 0; it < 2; it++) {
            int id = tid + it * 256;
            int r = id >> 2, c8 = (id & 3) << 3;
            uint4 v = *(const uint4*)(Bt + (size_t)(blockCol + r) * K + k0 + c8);
            *(uint4*)(Bs + r * GSTRIDE + c8) = v;
        }
        __syncthreads();

        #pragma unroll
        for (int k16 = 0; k16 < GBK; k16 += 16) {
            uint32_t af[4][4];
            #pragma unroll
            for (int mt = 0; mt < 4; mt++) {
                int rbase = warp_m * 64 + mt * 16;
                const __half* p0 = As + (rbase + gid) * GSTRIDE + k16 + tig * 2;
                const __half* p1 = As + (rbase + gid + 8) * GSTRIDE + k16 + tig * 2;
                af[mt][0] = *(const uint32_t*)p0;
                af[mt][1] = *(const uint32_t*)p1;
                af[mt][2] = *(const uint32_t*)(p0 + 8);
                af[mt][3] = *(const uint32_t*)(p1 + 8);
            }
            uint32_t bf[4][2];
            #pragma unroll
            for (int nt = 0; nt < 4; nt++) {
                int nrow = warp_n * 32 + nt * 8 + gid;
                const __half* p = Bs + nrow * GSTRIDE + k16 + tig * 2;
                bf[nt][0] = *(const uint32_t*)p;
                bf[nt][1] = *(const uint32_t*)(p + 8);
            }
            #pragma unroll
            for (int mt = 0; mt < 4; mt++)
                #pragma unroll
                for (int nt = 0; nt < 4; nt++) {
                    asm volatile(
                        "mma.sync.aligned.m16n8k16.row.col.f32.f16.f16.f32 "
                        "{%0,%1,%2,%3}, {%4,%5,%6,%7}, {%8,%9}, {%0,%1,%2,%3};"
                        : "+f"(acc[mt][nt][0]), "+f"(acc[mt][nt][1]),
                          "+f"(acc[mt][nt][2]), "+f"(acc[mt][nt][3])
                        : "r"(af[mt][0]), "r"(af[mt][1]), "r"(af[mt][2]), "r"(af[mt][3]),
                          "r"(bf[nt][0]), "r"(bf[nt][1]));
                }
        }
        __syncthreads();
    }

    #pragma unroll
    for (int mt = 0; mt < 4; mt++) {
        #pragma unroll
        for (int half = 0; half < 2; half++) {
            int row = blockRow + warp_m * 64 + mt * 16 + gid + half * 8;
            if (row >= M) continue;
            float rs = (mode == 1) ? rowscale[row] : 0.f;
            #pragma unroll
            for (int nt = 0; nt < 4; nt++) {
                int col = blockCol + warp_n * 32 + nt * 8 + tig * 2;
                float v0 = acc[mt][nt][half * 2 + 0];
                float v1 = acc[mt][nt][half * 2 + 1];
                if (mode == 1) {
                    v0 = fmaxf(fmaf(rs, bias[col],     v0), 0.f);
                    v1 = fmaxf(fmaf(rs, bias[col + 1], v1), 0.f);
                }
                *(__half2*)(outH + (size_t)row * N + col) = __floats2half2_rn(v0, v1);
            }
        }
    }
}

// ---------------- link scoring ----------------
__global__ __launch_bounds__(256)
void link_kernel(const int* __restrict__ link, const float* __restrict__ fcb,
                 float* __restrict__ out) {
    int i = blockIdx.x * 256 + threadIdx.x;
    if (i >= N_LINKS) return;
    int a = link[2 * i], b = link[2 * i + 1];
    float x = (g_zfc[a] + g_zfc[b]) * 0.5f + fcb[0];
    out[i] = 1.0f / (1.0f + __expf(-x));
}

// ---------------- launch ----------------
extern "C" void kernel_launch(void* const* d_in, const int* in_sizes, int n_in,
                              void* d_out, int out_size) {
    const float* X    = (const float*)d_in[0];
    const float* W1   = (const float*)d_in[1];
    const float* b1   = (const float*)d_in[2];
    const float* W2   = (const float*)d_in[3];
    const float* b2   = (const float*)d_in[4];
    const float* fcW  = (const float*)d_in[5];
    const float* fcb  = (const float*)d_in[6];
    const int*   incv = (const int*)d_in[7];
    const int*   ince = (const int*)d_in[8];
    const int*   link = (const int*)d_in[9];
    float* out = (float*)d_out;

    static float*  p_s   = nullptr;
    static __half* p_Xh  = nullptr;
    static __half* p_X2h = nullptr;
    static __half* p_hh  = nullptr;
    static __half* p_th  = nullptr;
    static __half* p_W1T = nullptr;
    static __half* p_W2T = nullptr;
    static cudaStream_t s2 = nullptr, s3 = nullptr;
    static cudaEvent_t evFork = nullptr, evB = nullptr, evScan = nullptr, evC = nullptr;
    if (!p_s) {
        cudaGetSymbolAddress((void**)&p_s,   g_s);
        cudaGetSymbolAddress((void**)&p_Xh,  g_Xh);
        cudaGetSymbolAddress((void**)&p_X2h, g_X2h);
        cudaGetSymbolAddress((void**)&p_hh,  g_hh);
        cudaGetSymbolAddress((void**)&p_th,  g_th);
        cudaGetSymbolAddress((void**)&p_W1T, g_W1T);
        cudaGetSymbolAddress((void**)&p_W2T, g_W2T);
        cudaStreamCreateWithFlags(&s2, cudaStreamNonBlocking);
        cudaStreamCreateWithFlags(&s3, cudaStreamNonBlocking);
        cudaEventCreateWithFlags(&evFork, cudaEventDisableTiming);
        cudaEventCreateWithFlags(&evB,    cudaEventDisableTiming);
        cudaEventCreateWithFlags(&evScan, cudaEventDisableTiming);
        cudaEventCreateWithFlags(&evC,    cudaEventDisableTiming);
    }

    const int TPB = 256;
    int inc_blocks    = (N_INC + TPB - 1) / TPB;
    int node_blocks   = (N_NODES + TPB - 1) / TPB;
    int edge_blocks   = (N_HEDGES + 1 + TPB - 1) / TPB;
    int warp_blocks_e = (N_HEDGES * 32 + TPB - 1) / TPB;
    int warp_blocks_n = (N_NODES * 32 + TPB - 1) / TPB;
    int wt_blocks     = (C1 * C2 + TPB - 1) / TPB;
    int xh_blocks     = ((N_NODES * C1 / 2) + TPB - 1) / TPB;
    int gemm_rows     = (N_NODES + 127) / 128;   // 782

    // ---- fork branch B: edge_off, Xh, weight transposes (independent of counts) ----
    cudaEventRecord(evFork, 0);
    cudaStreamWaitEvent(s2, evFork, 0);
    edge_off_kernel<<<edge_blocks, TPB, 0, s2>>>(ince);
    x_to_h_kernel<<<xh_blocks, TPB, 0, s2>>>(X, p_Xh);
    wt_kernel<<<wt_blocks, TPB, 0, s2>>>(W1, p_W1T, C1, C2);
    wt_kernel<<<wt_blocks, TPB, 0, s2>>>(W2, p_W2T, C2, C1);
    cudaEventRecord(evB, s2);

    // ---- main: node degrees + offsets ----
    zero_counts_kernel<<<node_blocks, TPB>>>();
    count_kernel<<<inc_blocks, TPB>>>(incv);
    node_scan_phase1<<<SCAN_BLOCKS, TPB>>>();
    node_scan_phase2<<<1, 128>>>();
    node_scan_phase3<<<SCAN_BLOCKS, TPB>>>();
    cudaEventRecord(evScan, 0);

    // ---- branch C (s3): CSR + te + s, overlapped with edge_agg1 on main ----
    cudaStreamWaitEvent(s3, evScan, 0);
    cudaStreamWaitEvent(s3, evB, 0);
    build_csr_kernel<<<inc_blocks, TPB, 0, s3>>>(incv, ince);
    te_kernel<<<node_blocks, TPB, 0, s3>>>(incv);
    s_kernel<<<node_blocks, TPB, 0, s3>>>();
    cudaEventRecord(evC, s3);

    // ---- main: edge aggregation layer 1 (needs Xh, edge_off, dvi) ----
    cudaStreamWaitEvent(0, evB, 0);
    edge_agg_h_kernel<<<warp_blocks_e, TPB>>>(p_Xh, incv);

    // ---- join branch C, then node agg + GEMMs + layer 2 ----
    cudaStreamWaitEvent(0, evC, 0);
    node_agg_h_kernel<<<warp_blocks_n, TPB>>>(p_X2h);
    {
        dim3 grid(gemm_rows, C2 / 128);
        gemm_mma_kernel<<<grid, 256>>>(p_X2h, p_W1T, N_NODES, C1, C2, 1, p_s, b1, p_hh);
    }
    {
        dim3 grid(gemm_rows, C1 / 128);
        gemm_mma_kernel<<<grid, 256>>>(p_hh, p_W2T, N_NODES, C2, C1, 0, nullptr, nullptr, p_th);
    }
    edge_agg_h_kernel<<<warp_blocks_e, TPB>>>(p_th, incv);
    node_agg_final_kernel<<<warp_blocks_n, TPB>>>(b2, fcW);
    link_kernel<<<(N_LINKS + TPB - 1) / TPB, TPB>>>(link, fcb, out);
    (void)in_sizes; (void)n_in; (void)out_size;
}